// round 2
// baseline (speedup 1.0000x reference)
#include <cuda_runtime.h>
#include <math.h>

#define BATCH   8192
#define STATE_N 1360
#define TIN     1488
#define TH      1024
#define ATOMS   51
#define ACTIONS 81
#define ADVN    (ACTIONS*ATOMS)   // 4131

// ------------------------- scratch (no cudaMalloc allowed) ------------------
__device__ __align__(16) float g_tin[(size_t)BATCH*TIN];
__device__ __align__(16) float g_pre[(size_t)BATCH*TH];
__device__ __align__(16) float g_h  [(size_t)BATCH*TH];
__device__ __align__(16) float g_vfc[(size_t)BATCH*512];
__device__ __align__(16) float g_afc[(size_t)BATCH*512];
__device__ __align__(16) float g_val[(size_t)BATCH*ATOMS];
__device__ __align__(16) float g_adv[(size_t)BATCH*ADVN];

// ------------------------- folded front-end operators -----------------------
__device__ float d_M[8*128];     // centered [embW;embB]
__device__ float d_G[64];        // M M^T / 128
__device__ float d_Mk[8*128];
__device__ float d_Mv[8*128];
__device__ float d_kb[128];
__device__ float d_vb[128];
__device__ float d_q0[128];
__device__ float d_kcls[128];
__device__ float d_vcls[128];
__device__ float d_A[32];        // per-head score weights (incl 1/sqrt(32))
__device__ float d_Cc[4];
__device__ float d_sc0[4];       // cls self-score
__device__ float d_Q[4096];      // [h][i][c] Mv folded with out_proj
__device__ float d_P1[512];      // v_cls folded
__device__ float d_P2[512];      // vb folded

// ============================================================================
// Setup fold. One block, 1024 threads, batch-independent.
// ============================================================================
__global__ void setup_kernel(const float* __restrict__ embW, const float* __restrict__ embB,
                             const float* __restrict__ lng,  const float* __restrict__ lnb,
                             const float* __restrict__ cls,  const float* __restrict__ ipW,
                             const float* __restrict__ ipb,  const float* __restrict__ opW)
{
    int tid = threadIdx.x;
    __shared__ float em[8];
    if (tid < 8) {
        float s = 0.f;
        if (tid < 7) { for (int c=0;c<128;c++) s += embW[tid*128+c]; }
        else         { for (int c=0;c<128;c++) s += embB[c]; }
        em[tid] = s * (1.f/128.f);
    }
    __syncthreads();
    if (tid < 128) {
        int c = tid;
        for (int f=0; f<7; f++) d_M[f*128+c] = embW[f*128+c] - em[f];
        d_M[7*128+c] = embB[c] - em[7];
    }
    __syncthreads();
    if (tid < 64) {
        int i = tid>>3, j = tid&7;
        float s = 0.f;
        for (int c=0;c<128;c++) s += d_M[i*128+c]*d_M[j*128+c];
        d_G[tid] = s * (1.f/128.f);
    }
    const float* Wq = ipW;
    const float* Wk = ipW + 128*128;
    const float* Wv = ipW + 256*128;
    for (int idx=tid; idx<1024; idx+=1024) {
        int i = idx>>7, c2 = idx&127;
        float sk=0.f, sv=0.f;
        for (int c=0;c<128;c++) {
            float mg = d_M[i*128+c]*lng[c];
            sk += mg*Wk[c2*128+c];
            sv += mg*Wv[c2*128+c];
        }
        d_Mk[idx] = sk; d_Mv[idx] = sv;
    }
    if (tid < 128) {
        int c2 = tid;
        float sk=0.f, sv=0.f, sq=0.f, skc=0.f, svc=0.f;
        for (int c=0;c<128;c++) {
            float bl = lnb[c], cl = cls[c];
            sk  += bl*Wk[c2*128+c];
            sv  += bl*Wv[c2*128+c];
            sq  += cl*Wq[c2*128+c];
            skc += cl*Wk[c2*128+c];
            svc += cl*Wv[c2*128+c];
        }
        d_kb[c2]   = sk  + ipb[128+c2];
        d_vb[c2]   = sv  + ipb[256+c2];
        d_q0[c2]   = sq  + ipb[c2];
        d_kcls[c2] = skc + ipb[128+c2];
        d_vcls[c2] = svc + ipb[256+c2];
    }
    __syncthreads();
    const float inv_s32 = 0.17677669529663687f;
    if (tid < 32) {
        int h = tid>>3, i = tid&7;
        float s = 0.f;
        for (int u=0;u<32;u++) s += d_Mk[i*128 + h*32+u]*d_q0[h*32+u];
        d_A[tid] = s*inv_s32;
    }
    if (tid >= 32 && tid < 36) {
        int h = tid-32; float s = 0.f;
        for (int u=0;u<32;u++) s += d_kb[h*32+u]*d_q0[h*32+u];
        d_Cc[h] = s*inv_s32;
    }
    if (tid >= 36 && tid < 40) {
        int h = tid-36; float s = 0.f;
        for (int u=0;u<32;u++) s += d_kcls[h*32+u]*d_q0[h*32+u];
        d_sc0[h] = s*inv_s32;
    }
    __syncthreads();
    for (int idx=tid; idx<4096; idx+=1024) {
        int h = idx>>10, i = (idx>>7)&7, c = idx&127;
        float s = 0.f;
        for (int u=0;u<32;u++) s += d_Mv[i*128 + h*32+u]*opW[c*128 + h*32+u];
        d_Q[idx] = s;
    }
    for (int idx=tid; idx<512; idx+=1024) {
        int h = idx>>7, c = idx&127;
        float s1=0.f, s2=0.f;
        for (int u=0;u<32;u++) {
            float w = opW[c*128 + h*32+u];
            s1 += d_vcls[h*32+u]*w;
            s2 += d_vb  [h*32+u]*w;
        }
        d_P1[idx] = s1; d_P2[idx] = s2;
    }
}

// ============================================================================
// Front: tokens -> collapsed attention -> pooled; also copies state into the
// trunk input buffer. 1 block per batch row, 128 threads (warp == head).
// ============================================================================
__global__ void front_kernel(const float* __restrict__ state, const float* __restrict__ opb)
{
    int b = blockIdx.x, tid = threadIdx.x;
    const float* srow = state + (size_t)b*STATE_N;
    float* trow = g_tin + (size_t)b*TIN;
    for (int i=tid; i<STATE_N; i+=128) trow[i] = srow[i];

    __shared__ float tokp[68][8];
    __shared__ float s_s[68];
    __shared__ int   smask[68];
    __shared__ int   s_ae;
    __shared__ float sy[4][8];
    __shared__ float sa0[4];

    if (tid < 68) {
        const int defs[9]  = {16,8,4,4,4,8,8,8,8};
        const int bases[9] = {59,124,157,174,191,208,241,274,307};
        int t = tid, cat = 0, start = 0;
        while (t >= start + defs[cat]) { start += defs[cat]; cat++; }
        int slot = t - start;
        int lo = 1020 + bases[cat] + 1 + slot*4;
        int po =  680 + bases[cat] + 1 + slot*4;
        float pr = srow[lo+0], dx = srow[lo+1], dy = srow[lo+2], ds = srow[lo+3];
        float pp = srow[po+0], px = srow[po+1], py = srow[po+2];
        float vv = (pr > 0.5f && pp > 0.5f) ? 1.f : 0.f;
        float tk[8];
        tk[0]=dx; tk[1]=dy; tk[2]=ds; tk[3]=(dx-px)*vv; tk[4]=(dy-py)*vv;
        tk[5]=(float)cat*0.125f; tk[6]=pr; tk[7]=1.f;
        #pragma unroll
        for (int i=0;i<8;i++) tokp[tid][i]=tk[i];
        float v = 0.f;
        #pragma unroll
        for (int i=0;i<8;i++)
            #pragma unroll
            for (int j=0;j<8;j++) v += tk[i]*tk[j]*d_G[i*8+j];
        v = fmaxf(v, 0.f);
        s_s[tid]   = rsqrtf(v + 1e-5f);
        smask[tid] = (pr < 0.5f) ? 1 : 0;
    }
    __syncthreads();
    if (tid == 0) {
        int ae = 1;
        for (int t=0;t<68;t++) ae &= smask[t];
        s_ae = ae;
    }
    __syncthreads();

    int w = tid>>5, lane = tid&31;
    float Ah[8];
    #pragma unroll
    for (int i=0;i<8;i++) Ah[i]=d_A[w*8+i];
    float Ch = d_Cc[w];
    float c0 = d_sc0[w];
    int   ae = s_ae;

    int t0i = lane, t1i = lane+32, t2i = lane+64;
    bool v2 = (t2i < 68);
    auto score = [&](int t)->float {
        if (smask[t] && !ae) return -1e9f;
        float acc = 0.f;
        #pragma unroll
        for (int i=0;i<8;i++) acc += tokp[t][i]*Ah[i];
        return s_s[t]*acc + Ch;
    };
    float sA = score(t0i);
    float sB = score(t1i);
    float sC = v2 ? score(t2i) : -1e9f;
    float mx = fmaxf(fmaxf(sA,sB), fmaxf(sC, c0));
    for (int o=16;o;o>>=1) mx = fmaxf(mx, __shfl_xor_sync(0xffffffffu, mx, o));
    float eA = expf(sA-mx), eB = expf(sB-mx), eC = v2 ? expf(sC-mx) : 0.f;
    float ecls = expf(c0-mx);
    float ssum = eA+eB+eC;
    for (int o=16;o;o>>=1) ssum += __shfl_xor_sync(0xffffffffu, ssum, o);
    float inv = 1.f/(ssum + ecls);
    float wA = eA*s_s[t0i], wB = eB*s_s[t1i], wC = v2 ? eC*s_s[t2i] : 0.f;
    #pragma unroll
    for (int i=0;i<8;i++) {
        float yy = wA*tokp[t0i][i] + wB*tokp[t1i][i];
        if (v2) yy += wC*tokp[t2i][i];
        for (int o=16;o;o>>=1) yy += __shfl_xor_sync(0xffffffffu, yy, o);
        if (lane==0) sy[w][i] = yy*inv;
    }
    if (lane==0) sa0[w] = ecls*inv;
    __syncthreads();

    {   // pooled[c]
        int c = tid;
        float acc = opb[c];
        #pragma unroll
        for (int h=0;h<4;h++) {
            float a0 = sa0[h];
            acc += a0*d_P1[h*128+c] + (1.f-a0)*d_P2[h*128+c];
            #pragma unroll
            for (int i=0;i<8;i++) acc += sy[h][i]*d_Q[(h*8+i)*128 + c];
        }
        trow[STATE_N + c] = acc;
    }
}

// ============================================================================
// SGEMM C[M,N] = A[M,K]@B[K,N] + bias, optional relu.
// 128x128 tile, BK=8, 256 threads, 8x8/thread. M%128==0, K%8==0 assumed.
// ============================================================================
__global__ __launch_bounds__(256, 2)
void sgemm_kernel(int M, int N, int K,
                  const float* __restrict__ A, int lda,
                  const float* __restrict__ B, int ldb,
                  float* __restrict__ C, int ldc,
                  const float* __restrict__ bias, int doRelu)
{
    __shared__ __align__(16) float As[8][128];
    __shared__ __align__(16) float Bs[8][132];
    int tid = threadIdx.x;
    int bm = blockIdx.y*128, bn = blockIdx.x*128;
    int tx = tid & 15, ty = tid >> 4;
    int ar = tid >> 1, aq = (tid & 1) * 4;
    int bk = tid >> 5, bn0 = (tid & 31) * 4;

    float acc[8][8];
    #pragma unroll
    for (int i=0;i<8;i++)
        #pragma unroll
        for (int j=0;j<8;j++) acc[i][j]=0.f;

    for (int k0 = 0; k0 < K; k0 += 8) {
        float4 av = *(const float4*)(A + (size_t)(bm + ar)*lda + k0 + aq);
        As[aq+0][ar] = av.x; As[aq+1][ar] = av.y;
        As[aq+2][ar] = av.z; As[aq+3][ar] = av.w;
        #pragma unroll
        for (int j = 0; j < 4; j++) {
            int n = bn + bn0 + j;
            Bs[bk][bn0+j] = (n < N) ? B[(size_t)(k0+bk)*ldb + n] : 0.f;
        }
        __syncthreads();
        #pragma unroll
        for (int kk = 0; kk < 8; kk++) {
            float a[8], bb[8];
            #pragma unroll
            for (int i = 0; i < 8; i++) a[i] = As[kk][ty*8+i];
            #pragma unroll
            for (int j = 0; j < 8; j++) bb[j] = Bs[kk][tx*8+j];
            #pragma unroll
            for (int i = 0; i < 8; i++)
                #pragma unroll
                for (int j = 0; j < 8; j++)
                    acc[i][j] = fmaf(a[i], bb[j], acc[i][j]);
        }
        __syncthreads();
    }
    #pragma unroll
    for (int i = 0; i < 8; i++) {
        int m = bm + ty*8 + i;
        #pragma unroll
        for (int j = 0; j < 8; j++) {
            int n = bn + tx*8 + j;
            if (n < N) {
                float v = acc[i][j] + bias[n];
                if (doRelu) v = fmaxf(v, 0.f);
                C[(size_t)m*ldc + n] = v;
            }
        }
    }
}

// ============================================================================
// LayerNorm + ReLU over rows of 1024. Block per row, 256 threads.
// ============================================================================
__global__ void ln_relu_kernel(const float* __restrict__ X, const float* __restrict__ g,
                               const float* __restrict__ beta, float* __restrict__ Y)
{
    int b = blockIdx.x, tid = threadIdx.x;
    const float* x = X + (size_t)b*TH;
    float* y = Y + (size_t)b*TH;
    float v[4], s = 0.f, s2 = 0.f;
    #pragma unroll
    for (int i=0;i<4;i++){ v[i]=x[tid + i*256]; s+=v[i]; s2+=v[i]*v[i]; }
    __shared__ float red[2][8];
    for (int o=16;o;o>>=1){ s += __shfl_xor_sync(0xffffffffu,s,o); s2 += __shfl_xor_sync(0xffffffffu,s2,o); }
    if ((tid&31)==0){ red[0][tid>>5]=s; red[1][tid>>5]=s2; }
    __syncthreads();
    float ts=0.f, ts2=0.f;
    #pragma unroll
    for (int w=0;w<8;w++){ ts+=red[0][w]; ts2+=red[1][w]; }
    float mean = ts*(1.f/TH);
    float var  = ts2*(1.f/TH) - mean*mean;
    float inv  = rsqrtf(var + 1e-5f);
    #pragma unroll
    for (int i=0;i<4;i++){
        int c = tid + i*256;
        float r = (v[i]-mean)*inv*g[c] + beta[c];
        y[c] = fmaxf(r, 0.f);
    }
}

// ============================================================================
// Dueling combine + softmax over atoms. Block per batch row, 256 threads.
// ============================================================================
__global__ void combine_kernel(const float* __restrict__ val, const float* __restrict__ adv,
                               float* __restrict__ out)
{
    int b = blockIdx.x, tid = threadIdx.x;
    __shared__ float sadv[ADVN];
    __shared__ float sval[ATOMS];
    __shared__ float cmean[ATOMS];
    const float* arow = adv + (size_t)b*ADVN;
    for (int i = tid; i < ADVN; i += 256) sadv[i] = arow[i];
    if (tid < ATOMS) sval[tid] = val[(size_t)b*ATOMS + tid];
    __syncthreads();
    if (tid < ATOMS) {
        float s = 0.f;
        for (int a = 0; a < ACTIONS; a++) s += sadv[a*ATOMS + tid];
        cmean[tid] = s * (1.f/ACTIONS);
    }
    __syncthreads();
    float* orow = out + (size_t)b*ADVN;
    for (int a = tid; a < ACTIONS; a += 256) {
        float q[ATOMS];
        float mx = -1e30f;
        #pragma unroll
        for (int t = 0; t < ATOMS; t++) {
            float qv = sval[t] + sadv[a*ATOMS+t] - cmean[t];
            q[t] = qv; mx = fmaxf(mx, qv);
        }
        float sum = 0.f;
        #pragma unroll
        for (int t = 0; t < ATOMS; t++) { float e = expf(q[t]-mx); q[t]=e; sum += e; }
        float inv = 1.f/sum;
        #pragma unroll
        for (int t = 0; t < ATOMS; t++) orow[a*ATOMS+t] = q[t]*inv;
    }
}

// ============================================================================
extern "C" void kernel_launch(void* const* d_in, const int* in_sizes, int n_in,
                              void* d_out, int out_size)
{
    const float* state = (const float*)d_in[0];
    const float* embW  = (const float*)d_in[1];
    const float* embB  = (const float*)d_in[2];
    const float* lng   = (const float*)d_in[3];
    const float* lnb   = (const float*)d_in[4];
    const float* cls   = (const float*)d_in[5];
    const float* ipW   = (const float*)d_in[6];
    const float* ipb   = (const float*)d_in[7];
    const float* opW   = (const float*)d_in[8];
    const float* opb   = (const float*)d_in[9];
    const float* t0W   = (const float*)d_in[10];
    const float* t0b   = (const float*)d_in[11];
    const float* t0g   = (const float*)d_in[12];
    const float* t0be  = (const float*)d_in[13];
    const float* t1W   = (const float*)d_in[14];
    const float* t1b   = (const float*)d_in[15];
    const float* t1g   = (const float*)d_in[16];
    const float* t1be  = (const float*)d_in[17];
    const float* vfW   = (const float*)d_in[18];
    const float* vfb   = (const float*)d_in[19];
    const float* voW   = (const float*)d_in[20];
    const float* vob   = (const float*)d_in[21];
    const float* afW   = (const float*)d_in[22];
    const float* afb   = (const float*)d_in[23];
    const float* aoW   = (const float*)d_in[24];
    const float* aob   = (const float*)d_in[25];
    float* out = (float*)d_out;

    float *tin, *pre, *h, *vfc, *afc, *valb, *advb;
    cudaGetSymbolAddress((void**)&tin,  g_tin);
    cudaGetSymbolAddress((void**)&pre,  g_pre);
    cudaGetSymbolAddress((void**)&h,    g_h);
    cudaGetSymbolAddress((void**)&vfc,  g_vfc);
    cudaGetSymbolAddress((void**)&afc,  g_afc);
    cudaGetSymbolAddress((void**)&valb, g_val);
    cudaGetSymbolAddress((void**)&advb, g_adv);

    setup_kernel<<<1, 1024>>>(embW, embB, lng, lnb, cls, ipW, ipb, opW);
    front_kernel<<<BATCH, 128>>>(state, opb);

    dim3 gt0((TH+127)/128, BATCH/128);
    sgemm_kernel<<<gt0, 256>>>(BATCH, TH, TIN, tin, TIN, t0W, TH, pre, TH, t0b, 0);
    ln_relu_kernel<<<BATCH, 256>>>(pre, t0g, t0be, h);

    dim3 gt1((TH+127)/128, BATCH/128);
    sgemm_kernel<<<gt1, 256>>>(BATCH, TH, TH, h, TH, t1W, TH, pre, TH, t1b, 0);
    ln_relu_kernel<<<BATCH, 256>>>(pre, t1g, t1be, h);

    dim3 gfc((512+127)/128, BATCH/128);
    sgemm_kernel<<<gfc, 256>>>(BATCH, 512, TH, h, TH, vfW, 512, vfc, 512, vfb, 1);
    sgemm_kernel<<<gfc, 256>>>(BATCH, 512, TH, h, TH, afW, 512, afc, 512, afb, 1);

    dim3 gvo((ATOMS+127)/128, BATCH/128);
    sgemm_kernel<<<gvo, 256>>>(BATCH, ATOMS, 512, vfc, 512, voW, ATOMS, valb, ATOMS, vob, 0);

    dim3 gao((ADVN+127)/128, BATCH/128);
    sgemm_kernel<<<gao, 256>>>(BATCH, ADVN, 512, afc, 512, aoW, ADVN, advb, ADVN, aob, 0);

    combine_kernel<<<BATCH, 256>>>(valb, advb, out);
}

// round 4
// speedup vs baseline: 1.7171x; 1.7171x over previous
#include <cuda_runtime.h>
#include <math.h>

#define BATCH   8192
#define STATE_N 1360
#define TIN     1488
#define TH      1024
#define ATOMS   51
#define ACTIONS 81
#define ADVN    (ACTIONS*ATOMS)   // 4131

typedef unsigned long long ull;

// ------------------------- scratch (no cudaMalloc allowed) ------------------
__device__ __align__(16) float g_tin[(size_t)BATCH*TIN];
__device__ __align__(16) float g_pre[(size_t)BATCH*TH];
__device__ __align__(16) float g_h  [(size_t)BATCH*TH];
__device__ __align__(16) float g_vfc[(size_t)BATCH*512];
__device__ __align__(16) float g_afc[(size_t)BATCH*512];
__device__ __align__(16) float g_val[(size_t)BATCH*ATOMS];
__device__ __align__(16) float g_adv[(size_t)BATCH*ADVN];

// ------------------------- folded front-end operators -----------------------
__device__ float d_M[8*128];
__device__ float d_G[64];
__device__ float d_Mk[8*128];
__device__ float d_Mv[8*128];
__device__ float d_kb[128];
__device__ float d_vb[128];
__device__ float d_q0[128];
__device__ float d_kcls[128];
__device__ float d_vcls[128];
__device__ float d_A[32];
__device__ float d_Cc[4];
__device__ float d_sc0[4];
__device__ float d_Q[4096];
__device__ float d_P1[512];
__device__ float d_P2[512];

// ============================================================================
// Setup fold. One block, 1024 threads, batch-independent.
// ============================================================================
__global__ void setup_kernel(const float* __restrict__ embW, const float* __restrict__ embB,
                             const float* __restrict__ lng,  const float* __restrict__ lnb,
                             const float* __restrict__ cls,  const float* __restrict__ ipW,
                             const float* __restrict__ ipb,  const float* __restrict__ opW)
{
    int tid = threadIdx.x;
    __shared__ float em[8];
    if (tid < 8) {
        float s = 0.f;
        if (tid < 7) { for (int c=0;c<128;c++) s += embW[tid*128+c]; }
        else         { for (int c=0;c<128;c++) s += embB[c]; }
        em[tid] = s * (1.f/128.f);
    }
    __syncthreads();
    if (tid < 128) {
        int c = tid;
        for (int f=0; f<7; f++) d_M[f*128+c] = embW[f*128+c] - em[f];
        d_M[7*128+c] = embB[c] - em[7];
    }
    __syncthreads();
    if (tid < 64) {
        int i = tid>>3, j = tid&7;
        float s = 0.f;
        for (int c=0;c<128;c++) s += d_M[i*128+c]*d_M[j*128+c];
        d_G[tid] = s * (1.f/128.f);
    }
    const float* Wq = ipW;
    const float* Wk = ipW + 128*128;
    const float* Wv = ipW + 256*128;
    for (int idx=tid; idx<1024; idx+=1024) {
        int i = idx>>7, c2 = idx&127;
        float sk=0.f, sv=0.f;
        for (int c=0;c<128;c++) {
            float mg = d_M[i*128+c]*lng[c];
            sk += mg*Wk[c2*128+c];
            sv += mg*Wv[c2*128+c];
        }
        d_Mk[idx] = sk; d_Mv[idx] = sv;
    }
    if (tid < 128) {
        int c2 = tid;
        float sk=0.f, sv=0.f, sq=0.f, skc=0.f, svc=0.f;
        for (int c=0;c<128;c++) {
            float bl = lnb[c], cl = cls[c];
            sk  += bl*Wk[c2*128+c];
            sv  += bl*Wv[c2*128+c];
            sq  += cl*Wq[c2*128+c];
            skc += cl*Wk[c2*128+c];
            svc += cl*Wv[c2*128+c];
        }
        d_kb[c2]   = sk  + ipb[128+c2];
        d_vb[c2]   = sv  + ipb[256+c2];
        d_q0[c2]   = sq  + ipb[c2];
        d_kcls[c2] = skc + ipb[128+c2];
        d_vcls[c2] = svc + ipb[256+c2];
    }
    __syncthreads();
    const float inv_s32 = 0.17677669529663687f;
    if (tid < 32) {
        int h = tid>>3, i = tid&7;
        float s = 0.f;
        for (int u=0;u<32;u++) s += d_Mk[i*128 + h*32+u]*d_q0[h*32+u];
        d_A[tid] = s*inv_s32;
    }
    if (tid >= 32 && tid < 36) {
        int h = tid-32; float s = 0.f;
        for (int u=0;u<32;u++) s += d_kb[h*32+u]*d_q0[h*32+u];
        d_Cc[h] = s*inv_s32;
    }
    if (tid >= 36 && tid < 40) {
        int h = tid-36; float s = 0.f;
        for (int u=0;u<32;u++) s += d_kcls[h*32+u]*d_q0[h*32+u];
        d_sc0[h] = s*inv_s32;
    }
    __syncthreads();
    for (int idx=tid; idx<4096; idx+=1024) {
        int h = idx>>10, i = (idx>>7)&7, c = idx&127;
        float s = 0.f;
        for (int u=0;u<32;u++) s += d_Mv[i*128 + h*32+u]*opW[c*128 + h*32+u];
        d_Q[idx] = s;
    }
    for (int idx=tid; idx<512; idx+=1024) {
        int h = idx>>7, c = idx&127;
        float s1=0.f, s2=0.f;
        for (int u=0;u<32;u++) {
            float w = opW[c*128 + h*32+u];
            s1 += d_vcls[h*32+u]*w;
            s2 += d_vb  [h*32+u]*w;
        }
        d_P1[idx] = s1; d_P2[idx] = s2;
    }
}

// ============================================================================
// Front: tokens -> collapsed attention -> pooled; copies state into trunk in.
// ============================================================================
__global__ void front_kernel(const float* __restrict__ state, const float* __restrict__ opb)
{
    int b = blockIdx.x, tid = threadIdx.x;
    const float* srow = state + (size_t)b*STATE_N;
    float* trow = g_tin + (size_t)b*TIN;
    for (int i=tid; i<STATE_N; i+=128) trow[i] = srow[i];

    __shared__ float tokp[68][8];
    __shared__ float s_s[68];
    __shared__ int   smask[68];
    __shared__ int   s_ae;
    __shared__ float sy[4][8];
    __shared__ float sa0[4];

    if (tid < 68) {
        const int defs[9]  = {16,8,4,4,4,8,8,8,8};
        const int bases[9] = {59,124,157,174,191,208,241,274,307};
        int t = tid, cat = 0, start = 0;
        while (t >= start + defs[cat]) { start += defs[cat]; cat++; }
        int slot = t - start;
        int lo = 1020 + bases[cat] + 1 + slot*4;
        int po =  680 + bases[cat] + 1 + slot*4;
        float pr = srow[lo+0], dx = srow[lo+1], dy = srow[lo+2], ds = srow[lo+3];
        float pp = srow[po+0], px = srow[po+1], py = srow[po+2];
        float vv = (pr > 0.5f && pp > 0.5f) ? 1.f : 0.f;
        float tk[8];
        tk[0]=dx; tk[1]=dy; tk[2]=ds; tk[3]=(dx-px)*vv; tk[4]=(dy-py)*vv;
        tk[5]=(float)cat*0.125f; tk[6]=pr; tk[7]=1.f;
        #pragma unroll
        for (int i=0;i<8;i++) tokp[tid][i]=tk[i];
        float v = 0.f;
        #pragma unroll
        for (int i=0;i<8;i++)
            #pragma unroll
            for (int j=0;j<8;j++) v += tk[i]*tk[j]*d_G[i*8+j];
        v = fmaxf(v, 0.f);
        s_s[tid]   = rsqrtf(v + 1e-5f);
        smask[tid] = (pr < 0.5f) ? 1 : 0;
    }
    __syncthreads();
    if (tid == 0) {
        int ae = 1;
        for (int t=0;t<68;t++) ae &= smask[t];
        s_ae = ae;
    }
    __syncthreads();

    int w = tid>>5, lane = tid&31;
    float Ah[8];
    #pragma unroll
    for (int i=0;i<8;i++) Ah[i]=d_A[w*8+i];
    float Ch = d_Cc[w];
    float c0 = d_sc0[w];
    int   ae = s_ae;

    int t0i = lane, t1i = lane+32, t2i = lane+64;
    bool v2 = (t2i < 68);
    auto score = [&](int t)->float {
        if (smask[t] && !ae) return -1e9f;
        float acc = 0.f;
        #pragma unroll
        for (int i=0;i<8;i++) acc += tokp[t][i]*Ah[i];
        return s_s[t]*acc + Ch;
    };
    float sA = score(t0i);
    float sB = score(t1i);
    float sC = v2 ? score(t2i) : -1e9f;
    float mx = fmaxf(fmaxf(sA,sB), fmaxf(sC, c0));
    for (int o=16;o;o>>=1) mx = fmaxf(mx, __shfl_xor_sync(0xffffffffu, mx, o));
    float eA = expf(sA-mx), eB = expf(sB-mx), eC = v2 ? expf(sC-mx) : 0.f;
    float ecls = expf(c0-mx);
    float ssum = eA+eB+eC;
    for (int o=16;o;o>>=1) ssum += __shfl_xor_sync(0xffffffffu, ssum, o);
    float inv = 1.f/(ssum + ecls);
    float wA = eA*s_s[t0i], wB = eB*s_s[t1i], wC = v2 ? eC*s_s[t2i] : 0.f;
    #pragma unroll
    for (int i=0;i<8;i++) {
        float yy = wA*tokp[t0i][i] + wB*tokp[t1i][i];
        if (v2) yy += wC*tokp[t2i][i];
        for (int o=16;o;o>>=1) yy += __shfl_xor_sync(0xffffffffu, yy, o);
        if (lane==0) sy[w][i] = yy*inv;
    }
    if (lane==0) sa0[w] = ecls*inv;
    __syncthreads();

    {
        int c = tid;
        float acc = opb[c];
        #pragma unroll
        for (int h=0;h<4;h++) {
            float a0 = sa0[h];
            acc += a0*d_P1[h*128+c] + (1.f-a0)*d_P2[h*128+c];
            #pragma unroll
            for (int i=0;i<8;i++) acc += sy[h][i]*d_Q[(h*8+i)*128 + c];
        }
        trow[STATE_N + c] = acc;
    }
}

// ============================================================================
// f32x2 packed helpers (FFMA2 — only reachable via PTX)
// ============================================================================
__device__ __forceinline__ ull pk2(float lo, float hi) {
    ull r; asm("mov.b64 %0, {%1, %2};" : "=l"(r) : "f"(lo), "f"(hi)); return r;
}
__device__ __forceinline__ void fma2(ull &d, ull a, ull b) {
    asm("fma.rn.f32x2 %0, %1, %2, %0;" : "+l"(d) : "l"(a), "l"(b));
}
__device__ __forceinline__ float2 up2(ull v) {
    float2 r; asm("mov.b64 {%0, %1}, %2;" : "=f"(r.x), "=f"(r.y) : "l"(v)); return r;
}

// ============================================================================
// SGEMM C[M,N] = A[M,K]@B[K,N] + bias, optional relu.
// 128x128 tile, BK=8, 256 threads, 8x8/thread, f32x2 accumulators,
// double-buffered smem (one barrier per K-step). M%128==0, K%8==0, lda%4==0.
// ============================================================================
__global__ __launch_bounds__(256, 2)
void sgemm2_kernel(int M, int N, int K,
                   const float* __restrict__ A, int lda,
                   const float* __restrict__ B, int ldb,
                   float* __restrict__ C, int ldc,
                   const float* __restrict__ bias, int doRelu)
{
    __shared__ __align__(16) float As[2][8][128];
    __shared__ __align__(16) float Bs[2][8][128];
    int tid = threadIdx.x;
    int bm = blockIdx.y*128, bn = blockIdx.x*128;
    int tx = tid & 15, ty = tid >> 4;
    int ar = tid >> 1, aq = (tid & 1) * 4;
    int bk = tid >> 5, bn0 = (tid & 31) * 4;
    bool bfast = ((ldb & 3) == 0) && (bn + 128 <= N);

    ull acc[8][4];
    #pragma unroll
    for (int i=0;i<8;i++)
        #pragma unroll
        for (int p=0;p<4;p++) acc[i][p]=0ull;

    const float* Aptr = A + (size_t)(bm + ar)*lda + aq;
    const float* Bptr = B + (size_t)bk*ldb;

    // preload tile 0
    {
        float4 av = *(const float4*)(Aptr);
        As[0][aq+0][ar]=av.x; As[0][aq+1][ar]=av.y;
        As[0][aq+2][ar]=av.z; As[0][aq+3][ar]=av.w;
        if (bfast) {
            *(float4*)&Bs[0][bk][bn0] = *(const float4*)(Bptr + bn + bn0);
        } else {
            #pragma unroll
            for (int j=0;j<4;j++) {
                int n = bn + bn0 + j;
                Bs[0][bk][bn0+j] = (n < N) ? Bptr[n] : 0.f;
            }
        }
    }
    __syncthreads();

    int cur = 0;
    for (int k0 = 0; k0 < K; k0 += 8) {
        bool more = (k0 + 8 < K);
        float4 nav; float4 nbv; float nb[4];
        if (more) {
            nav = *(const float4*)(Aptr + k0 + 8);
            if (bfast) nbv = *(const float4*)(Bptr + (size_t)(k0+8)*ldb + bn + bn0);
            else {
                #pragma unroll
                for (int j=0;j<4;j++) {
                    int n = bn + bn0 + j;
                    nb[j] = (n < N) ? Bptr[(size_t)(k0+8)*ldb + n] : 0.f;
                }
            }
        }
        #pragma unroll
        for (int kk = 0; kk < 8; kk++) {
            float4 a0 = *(const float4*)&As[cur][kk][ty*8];
            float4 a1 = *(const float4*)&As[cur][kk][ty*8+4];
            float4 b0 = *(const float4*)&Bs[cur][kk][tx*8];
            float4 b1 = *(const float4*)&Bs[cur][kk][tx*8+4];
            ull bp0 = pk2(b0.x, b0.y), bp1 = pk2(b0.z, b0.w);
            ull bp2 = pk2(b1.x, b1.y), bp3 = pk2(b1.z, b1.w);
            float a[8] = {a0.x,a0.y,a0.z,a0.w,a1.x,a1.y,a1.z,a1.w};
            #pragma unroll
            for (int i = 0; i < 8; i++) {
                ull ap = pk2(a[i], a[i]);
                fma2(acc[i][0], ap, bp0);
                fma2(acc[i][1], ap, bp1);
                fma2(acc[i][2], ap, bp2);
                fma2(acc[i][3], ap, bp3);
            }
        }
        if (more) {
            int nx = cur ^ 1;
            As[nx][aq+0][ar]=nav.x; As[nx][aq+1][ar]=nav.y;
            As[nx][aq+2][ar]=nav.z; As[nx][aq+3][ar]=nav.w;
            if (bfast) *(float4*)&Bs[nx][bk][bn0] = nbv;
            else {
                #pragma unroll
                for (int j=0;j<4;j++) Bs[nx][bk][bn0+j] = nb[j];
            }
        }
        __syncthreads();
        cur ^= 1;
    }

    // epilogue
    #pragma unroll
    for (int i = 0; i < 8; i++) {
        int m = bm + ty*8 + i;
        float* Crow = C + (size_t)m*ldc;
        #pragma unroll
        for (int p = 0; p < 4; p++) {
            float2 v = up2(acc[i][p]);
            int n0 = bn + tx*8 + 2*p;
            if (n0 < N) {
                float r = v.x + bias[n0];
                if (doRelu) r = fmaxf(r, 0.f);
                Crow[n0] = r;
            }
            if (n0+1 < N) {
                float r = v.y + bias[n0+1];
                if (doRelu) r = fmaxf(r, 0.f);
                Crow[n0+1] = r;
            }
        }
    }
}

// ============================================================================
// LayerNorm + ReLU over rows of 1024. Block per row, 256 threads.
// ============================================================================
__global__ void ln_relu_kernel(const float* __restrict__ X, const float* __restrict__ g,
                               const float* __restrict__ beta, float* __restrict__ Y)
{
    int b = blockIdx.x, tid = threadIdx.x;
    const float* x = X + (size_t)b*TH;
    float* y = Y + (size_t)b*TH;
    float v[4], s = 0.f, s2 = 0.f;
    #pragma unroll
    for (int i=0;i<4;i++){ v[i]=x[tid + i*256]; s+=v[i]; s2+=v[i]*v[i]; }
    __shared__ float red[2][8];
    for (int o=16;o;o>>=1){ s += __shfl_xor_sync(0xffffffffu,s,o); s2 += __shfl_xor_sync(0xffffffffu,s2,o); }
    if ((tid&31)==0){ red[0][tid>>5]=s; red[1][tid>>5]=s2; }
    __syncthreads();
    float ts=0.f, ts2=0.f;
    #pragma unroll
    for (int w=0;w<8;w++){ ts+=red[0][w]; ts2+=red[1][w]; }
    float mean = ts*(1.f/TH);
    float var  = ts2*(1.f/TH) - mean*mean;
    float inv  = rsqrtf(var + 1e-5f);
    #pragma unroll
    for (int i=0;i<4;i++){
        int c = tid + i*256;
        float r = (v[i]-mean)*inv*g[c] + beta[c];
        y[c] = fmaxf(r, 0.f);
    }
}

// ============================================================================
// Dueling combine + softmax over atoms. Block per batch row, 256 threads.
// ============================================================================
__global__ void combine_kernel(const float* __restrict__ val, const float* __restrict__ adv,
                               float* __restrict__ out)
{
    int b = blockIdx.x, tid = threadIdx.x;
    __shared__ float sadv[ADVN];
    __shared__ float sval[ATOMS];
    __shared__ float cmean[ATOMS];
    const float* arow = adv + (size_t)b*ADVN;
    for (int i = tid; i < ADVN; i += 256) sadv[i] = arow[i];
    if (tid < ATOMS) sval[tid] = val[(size_t)b*ATOMS + tid];
    __syncthreads();
    if (tid < ATOMS) {
        float s = 0.f;
        for (int a = 0; a < ACTIONS; a++) s += sadv[a*ATOMS + tid];
        cmean[tid] = s * (1.f/ACTIONS);
    }
    __syncthreads();
    float* orow = out + (size_t)b*ADVN;
    for (int a = tid; a < ACTIONS; a += 256) {
        float q[ATOMS];
        float mx = -1e30f;
        #pragma unroll
        for (int t = 0; t < ATOMS; t++) {
            float qv = sval[t] + sadv[a*ATOMS+t] - cmean[t];
            q[t] = qv; mx = fmaxf(mx, qv);
        }
        float sum = 0.f;
        #pragma unroll
        for (int t = 0; t < ATOMS; t++) { float e = expf(q[t]-mx); q[t]=e; sum += e; }
        float inv = 1.f/sum;
        #pragma unroll
        for (int t = 0; t < ATOMS; t++) orow[a*ATOMS+t] = q[t]*inv;
    }
}

// ============================================================================
extern "C" void kernel_launch(void* const* d_in, const int* in_sizes, int n_in,
                              void* d_out, int out_size)
{
    const float* state = (const float*)d_in[0];
    const float* embW  = (const float*)d_in[1];
    const float* embB  = (const float*)d_in[2];
    const float* lng   = (const float*)d_in[3];
    const float* lnb   = (const float*)d_in[4];
    const float* cls   = (const float*)d_in[5];
    const float* ipW   = (const float*)d_in[6];
    const float* ipb   = (const float*)d_in[7];
    const float* opW   = (const float*)d_in[8];
    const float* opb   = (const float*)d_in[9];
    const float* t0W   = (const float*)d_in[10];
    const float* t0b   = (const float*)d_in[11];
    const float* t0g   = (const float*)d_in[12];
    const float* t0be  = (const float*)d_in[13];
    const float* t1W   = (const float*)d_in[14];
    const float* t1b   = (const float*)d_in[15];
    const float* t1g   = (const float*)d_in[16];
    const float* t1be  = (const float*)d_in[17];
    const float* vfW   = (const float*)d_in[18];
    const float* vfb   = (const float*)d_in[19];
    const float* voW   = (const float*)d_in[20];
    const float* vob   = (const float*)d_in[21];
    const float* afW   = (const float*)d_in[22];
    const float* afb   = (const float*)d_in[23];
    const float* aoW   = (const float*)d_in[24];
    const float* aob   = (const float*)d_in[25];
    float* out = (float*)d_out;

    float *tin, *pre, *h, *vfc, *afc, *valb, *advb;
    cudaGetSymbolAddress((void**)&tin,  g_tin);
    cudaGetSymbolAddress((void**)&pre,  g_pre);
    cudaGetSymbolAddress((void**)&h,    g_h);
    cudaGetSymbolAddress((void**)&vfc,  g_vfc);
    cudaGetSymbolAddress((void**)&afc,  g_afc);
    cudaGetSymbolAddress((void**)&valb, g_val);
    cudaGetSymbolAddress((void**)&advb, g_adv);

    setup_kernel<<<1, 1024>>>(embW, embB, lng, lnb, cls, ipW, ipb, opW);
    front_kernel<<<BATCH, 128>>>(state, opb);

    dim3 gt0((TH+127)/128, BATCH/128);
    sgemm2_kernel<<<gt0, 256>>>(BATCH, TH, TIN, tin, TIN, t0W, TH, pre, TH, t0b, 0);
    ln_relu_kernel<<<BATCH, 256>>>(pre, t0g, t0be, h);

    dim3 gt1((TH+127)/128, BATCH/128);
    sgemm2_kernel<<<gt1, 256>>>(BATCH, TH, TH, h, TH, t1W, TH, pre, TH, t1b, 0);
    ln_relu_kernel<<<BATCH, 256>>>(pre, t1g, t1be, h);

    dim3 gfc((512+127)/128, BATCH/128);
    sgemm2_kernel<<<gfc, 256>>>(BATCH, 512, TH, h, TH, vfW, 512, vfc, 512, vfb, 1);
    sgemm2_kernel<<<gfc, 256>>>(BATCH, 512, TH, h, TH, afW, 512, afc, 512, afb, 1);

    dim3 gvo((ATOMS+127)/128, BATCH/128);
    sgemm2_kernel<<<gvo, 256>>>(BATCH, ATOMS, 512, vfc, 512, voW, ATOMS, valb, ATOMS, vob, 0);

    dim3 gao((ADVN+127)/128, BATCH/128);
    sgemm2_kernel<<<gao, 256>>>(BATCH, ADVN, 512, afc, 512, aoW, ADVN, advb, ADVN, aob, 0);

    combine_kernel<<<BATCH, 256>>>(valb, advb, out);
}

// round 7
// speedup vs baseline: 3.7522x; 2.1852x over previous
#include <cuda_runtime.h>
#include <math.h>
#include <stdint.h>

#define BATCH   8192
#define STATE_N 1360
#define TIN_PAD 1536
#define TH      1024
#define ATOMS   51
#define ACTIONS 81
#define ADVN    (ACTIONS*ATOMS)   // 4131
#define ADVP    4224              // 33*128

// ------------------------- scratch (no cudaMalloc allowed) ------------------
__device__ __align__(16) float g_tin[(size_t)BATCH*TIN_PAD];
__device__ __align__(16) float g_pre[(size_t)BATCH*TH];
__device__ __align__(16) float g_h  [(size_t)BATCH*TH];
__device__ __align__(16) float g_vfc[(size_t)BATCH*512];
__device__ __align__(16) float g_afc[(size_t)BATCH*512];
__device__ __align__(16) float g_val[(size_t)BATCH*128];
__device__ __align__(16) float g_adv[(size_t)BATCH*ADVP];
// transposed (K-major, padded) weights
__device__ __align__(16) float g_t0Wt[(size_t)1024*TIN_PAD];
__device__ __align__(16) float g_t1Wt[(size_t)1024*1024];
__device__ __align__(16) float g_vfWt[(size_t)512*1024];
__device__ __align__(16) float g_afWt[(size_t)512*1024];
__device__ __align__(16) float g_voWt[(size_t)128*512];
__device__ __align__(16) float g_aoWt[(size_t)ADVP*512];

// ------------------------- folded front-end operators -----------------------
__device__ float d_M[8*128];
__device__ float d_G[64];
__device__ float d_Mk[8*128];
__device__ float d_Mv[8*128];
__device__ float d_kb[128];
__device__ float d_vb[128];
__device__ float d_q0[128];
__device__ float d_kcls[128];
__device__ float d_vcls[128];
__device__ float d_A[32];
__device__ float d_Cc[4];
__device__ float d_sc0[4];
__device__ float d_Q[4096];
__device__ float d_P1[512];
__device__ float d_P2[512];

// ============================================================================
// Setup fold. One block, 1024 threads, batch-independent.
// ============================================================================
__global__ void setup_kernel(const float* __restrict__ embW, const float* __restrict__ embB,
                             const float* __restrict__ lng,  const float* __restrict__ lnb,
                             const float* __restrict__ cls,  const float* __restrict__ ipW,
                             const float* __restrict__ ipb,  const float* __restrict__ opW)
{
    int tid = threadIdx.x;
    __shared__ float em[8];
    if (tid < 8) {
        float s = 0.f;
        if (tid < 7) { for (int c=0;c<128;c++) s += embW[tid*128+c]; }
        else         { for (int c=0;c<128;c++) s += embB[c]; }
        em[tid] = s * (1.f/128.f);
    }
    __syncthreads();
    if (tid < 128) {
        int c = tid;
        for (int f=0; f<7; f++) d_M[f*128+c] = embW[f*128+c] - em[f];
        d_M[7*128+c] = embB[c] - em[7];
    }
    __syncthreads();
    if (tid < 64) {
        int i = tid>>3, j = tid&7;
        float s = 0.f;
        for (int c=0;c<128;c++) s += d_M[i*128+c]*d_M[j*128+c];
        d_G[tid] = s * (1.f/128.f);
    }
    const float* Wq = ipW;
    const float* Wk = ipW + 128*128;
    const float* Wv = ipW + 256*128;
    for (int idx=tid; idx<1024; idx+=1024) {
        int i = idx>>7, c2 = idx&127;
        float sk=0.f, sv=0.f;
        for (int c=0;c<128;c++) {
            float mg = d_M[i*128+c]*lng[c];
            sk += mg*Wk[c2*128+c];
            sv += mg*Wv[c2*128+c];
        }
        d_Mk[idx] = sk; d_Mv[idx] = sv;
    }
    if (tid < 128) {
        int c2 = tid;
        float sk=0.f, sv=0.f, sq=0.f, skc=0.f, svc=0.f;
        for (int c=0;c<128;c++) {
            float bl = lnb[c], cl = cls[c];
            sk  += bl*Wk[c2*128+c];
            sv  += bl*Wv[c2*128+c];
            sq  += cl*Wq[c2*128+c];
            skc += cl*Wk[c2*128+c];
            svc += cl*Wv[c2*128+c];
        }
        d_kb[c2]   = sk  + ipb[128+c2];
        d_vb[c2]   = sv  + ipb[256+c2];
        d_q0[c2]   = sq  + ipb[c2];
        d_kcls[c2] = skc + ipb[128+c2];
        d_vcls[c2] = svc + ipb[256+c2];
    }
    __syncthreads();
    const float inv_s32 = 0.17677669529663687f;
    if (tid < 32) {
        int h = tid>>3, i = tid&7;
        float s = 0.f;
        for (int u=0;u<32;u++) s += d_Mk[i*128 + h*32+u]*d_q0[h*32+u];
        d_A[tid] = s*inv_s32;
    }
    if (tid >= 32 && tid < 36) {
        int h = tid-32; float s = 0.f;
        for (int u=0;u<32;u++) s += d_kb[h*32+u]*d_q0[h*32+u];
        d_Cc[h] = s*inv_s32;
    }
    if (tid >= 36 && tid < 40) {
        int h = tid-36; float s = 0.f;
        for (int u=0;u<32;u++) s += d_kcls[h*32+u]*d_q0[h*32+u];
        d_sc0[h] = s*inv_s32;
    }
    __syncthreads();
    for (int idx=tid; idx<4096; idx+=1024) {
        int h = idx>>10, i = (idx>>7)&7, c = idx&127;
        float s = 0.f;
        for (int u=0;u<32;u++) s += d_Mv[i*128 + h*32+u]*opW[c*128 + h*32+u];
        d_Q[idx] = s;
    }
    for (int idx=tid; idx<512; idx+=1024) {
        int h = idx>>7, c = idx&127;
        float s1=0.f, s2=0.f;
        for (int u=0;u<32;u++) {
            float w = opW[c*128 + h*32+u];
            s1 += d_vcls[h*32+u]*w;
            s2 += d_vb  [h*32+u]*w;
        }
        d_P1[idx] = s1; d_P2[idx] = s2;
    }
}

// ============================================================================
// Front: collapsed attention -> pooled; copies state; zero-pads K to 1536.
// ============================================================================
__global__ void front_kernel(const float* __restrict__ state, const float* __restrict__ opb)
{
    int b = blockIdx.x, tid = threadIdx.x;
    const float* srow = state + (size_t)b*STATE_N;
    float* trow = g_tin + (size_t)b*TIN_PAD;
    for (int i=tid; i<STATE_N; i+=128) trow[i] = srow[i];
    if (tid < 48) trow[1488 + tid] = 0.f;

    __shared__ float tokp[68][8];
    __shared__ float s_s[68];
    __shared__ int   smask[68];
    __shared__ int   s_ae;
    __shared__ float sy[4][8];
    __shared__ float sa0[4];

    if (tid < 68) {
        const int defs[9]  = {16,8,4,4,4,8,8,8,8};
        const int bases[9] = {59,124,157,174,191,208,241,274,307};
        int t = tid, cat = 0, start = 0;
        while (t >= start + defs[cat]) { start += defs[cat]; cat++; }
        int slot = t - start;
        int lo = 1020 + bases[cat] + 1 + slot*4;
        int po =  680 + bases[cat] + 1 + slot*4;
        float pr = srow[lo+0], dx = srow[lo+1], dy = srow[lo+2], ds = srow[lo+3];
        float pp = srow[po+0], px = srow[po+1], py = srow[po+2];
        float vv = (pr > 0.5f && pp > 0.5f) ? 1.f : 0.f;
        float tk[8];
        tk[0]=dx; tk[1]=dy; tk[2]=ds; tk[3]=(dx-px)*vv; tk[4]=(dy-py)*vv;
        tk[5]=(float)cat*0.125f; tk[6]=pr; tk[7]=1.f;
        #pragma unroll
        for (int i=0;i<8;i++) tokp[tid][i]=tk[i];
        float v = 0.f;
        #pragma unroll
        for (int i=0;i<8;i++)
            #pragma unroll
            for (int j=0;j<8;j++) v += tk[i]*tk[j]*d_G[i*8+j];
        v = fmaxf(v, 0.f);
        s_s[tid]   = rsqrtf(v + 1e-5f);
        smask[tid] = (pr < 0.5f) ? 1 : 0;
    }
    __syncthreads();
    if (tid == 0) {
        int ae = 1;
        for (int t=0;t<68;t++) ae &= smask[t];
        s_ae = ae;
    }
    __syncthreads();

    int w = tid>>5, lane = tid&31;
    float Ah[8];
    #pragma unroll
    for (int i=0;i<8;i++) Ah[i]=d_A[w*8+i];
    float Ch = d_Cc[w];
    float c0 = d_sc0[w];
    int   ae = s_ae;

    int t0i = lane, t1i = lane+32, t2i = lane+64;
    bool v2 = (t2i < 68);
    auto score = [&](int t)->float {
        if (smask[t] && !ae) return -1e9f;
        float acc = 0.f;
        #pragma unroll
        for (int i=0;i<8;i++) acc += tokp[t][i]*Ah[i];
        return s_s[t]*acc + Ch;
    };
    float sA = score(t0i);
    float sB = score(t1i);
    float sC = v2 ? score(t2i) : -1e9f;
    float mx = fmaxf(fmaxf(sA,sB), fmaxf(sC, c0));
    for (int o=16;o;o>>=1) mx = fmaxf(mx, __shfl_xor_sync(0xffffffffu, mx, o));
    float eA = expf(sA-mx), eB = expf(sB-mx), eC = v2 ? expf(sC-mx) : 0.f;
    float ecls = expf(c0-mx);
    float ssum = eA+eB+eC;
    for (int o=16;o;o>>=1) ssum += __shfl_xor_sync(0xffffffffu, ssum, o);
    float inv = 1.f/(ssum + ecls);
    float wA = eA*s_s[t0i], wB = eB*s_s[t1i], wC = v2 ? eC*s_s[t2i] : 0.f;
    #pragma unroll
    for (int i=0;i<8;i++) {
        float yy = wA*tokp[t0i][i] + wB*tokp[t1i][i];
        if (v2) yy += wC*tokp[t2i][i];
        for (int o=16;o;o>>=1) yy += __shfl_xor_sync(0xffffffffu, yy, o);
        if (lane==0) sy[w][i] = yy*inv;
    }
    if (lane==0) sa0[w] = ecls*inv;
    __syncthreads();

    {
        int c = tid;
        float acc = opb[c];
        #pragma unroll
        for (int h=0;h<4;h++) {
            float a0 = sa0[h];
            acc += a0*d_P1[h*128+c] + (1.f-a0)*d_P2[h*128+c];
            #pragma unroll
            for (int i=0;i<8;i++) acc += sy[h][i]*d_Q[(h*8+i)*128 + c];
        }
        trow[STATE_N + c] = acc;
    }
}

// ============================================================================
// Transpose + pad: W[K][N] row-major -> Wt[NP][KP] (K-major rows, zero pad)
// ============================================================================
__global__ void transpose_pad_kernel(const float* __restrict__ W, int K, int N,
                                     float* __restrict__ Wt, int KP)
{
    __shared__ float t[32][33];
    int k0 = blockIdx.x*32, n0 = blockIdx.y*32;
    for (int i = threadIdx.y; i < 32; i += 8) {
        int k = k0 + i, n = n0 + threadIdx.x;
        t[i][threadIdx.x] = (k < K && n < N) ? W[(size_t)k*N + n] : 0.f;
    }
    __syncthreads();
    for (int i = threadIdx.y; i < 32; i += 8) {
        int n = n0 + i, k = k0 + threadIdx.x;
        Wt[(size_t)n*KP + k] = t[threadIdx.x][i];
    }
}

// ============================================================================
// tf32 mma.sync GEMM: C[M,NP] = A[M,K] @ Bt[NP,K]^T + bias (opt relu)
// block 128x128, BK=32, 256 threads (8 warps, 4m x 2n), warp tile 32x64.
// mma.sync.m16n8k8 tf32, fp32 accum. K%32==0, M%128==0, NP%128==0, ldc%2==0.
// ============================================================================
#define SPAD 36

__device__ __forceinline__ uint32_t tf32r(float x) {
    uint32_t r; asm("cvt.rna.tf32.f32 %0, %1;" : "=r"(r) : "f"(x)); return r;
}
__device__ __forceinline__ void mma8(float* c, const uint32_t* a, uint32_t b0, uint32_t b1) {
    asm volatile("mma.sync.aligned.m16n8k8.row.col.f32.tf32.tf32.f32 "
        "{%0,%1,%2,%3}, {%4,%5,%6,%7}, {%8,%9}, {%0,%1,%2,%3};"
        : "+f"(c[0]), "+f"(c[1]), "+f"(c[2]), "+f"(c[3])
        : "r"(a[0]), "r"(a[1]), "r"(a[2]), "r"(a[3]), "r"(b0), "r"(b1));
}

__global__ __launch_bounds__(256)
void mma_gemm_kernel(int K, const float* __restrict__ A, int lda,
                     const float* __restrict__ Bt,
                     float* __restrict__ C, int ldc, int Nreal,
                     const float* __restrict__ bias, int doRelu)
{
    __shared__ uint32_t As[128][SPAD];
    __shared__ uint32_t Bs[128][SPAD];

    int tid = threadIdx.x;
    int wid = tid >> 5, lane = tid & 31;
    int g = lane >> 2, t = lane & 3;
    int wm32 = (wid & 3) * 32;
    int wn64 = (wid >> 2) * 64;
    int bm = blockIdx.y * 128, bn = blockIdx.x * 128;

    // global load geometry: 4 float4 per operand per thread per BK step
    int lrow = tid >> 3;       // 0..31 (plus i*32)
    int lc4  = tid & 7;        // float4 index within 32-wide K slice
    const float* Ap = A  + (size_t)(bm + lrow)*lda + lc4*4;
    const float* Bp = Bt + (size_t)(bn + lrow)*K   + lc4*4;

    float acc[2][8][4];
    #pragma unroll
    for (int mf=0;mf<2;mf++)
        #pragma unroll
        for (int nf=0;nf<8;nf++)
            #pragma unroll
            for (int e=0;e<4;e++) acc[mf][nf][e]=0.f;

    int nsteps = K >> 5;
    float4 pa[4], pb[4];
    #pragma unroll
    for (int i=0;i<4;i++) {
        pa[i] = *(const float4*)(Ap + (size_t)(i*32)*lda);
        pb[i] = *(const float4*)(Bp + (size_t)(i*32)*K);
    }

    for (int s = 0; s < nsteps; s++) {
        // store (converted to tf32) into smem
        #pragma uroll
        #pragma unroll
        for (int i=0;i<4;i++) {
            uint32_t* da = &As[lrow + i*32][lc4*4];
            da[0]=tf32r(pa[i].x); da[1]=tf32r(pa[i].y); da[2]=tf32r(pa[i].z); da[3]=tf32r(pa[i].w);
            uint32_t* db = &Bs[lrow + i*32][lc4*4];
            db[0]=tf32r(pb[i].x); db[1]=tf32r(pb[i].y); db[2]=tf32r(pb[i].z); db[3]=tf32r(pb[i].w);
        }
        __syncthreads();
        // prefetch next BK
        if (s + 1 < nsteps) {
            size_t k0 = (size_t)(s + 1) << 5;
            #pragma unroll
            for (int i=0;i<4;i++) {
                pa[i] = *(const float4*)(Ap + (size_t)(i*32)*lda + k0);
                pb[i] = *(const float4*)(Bp + (size_t)(i*32)*K   + k0);
            }
        }
        // compute: 4 k8 sub-steps
        #pragma unroll
        for (int j=0;j<4;j++) {
            uint32_t a[2][4];
            #pragma unroll
            for (int mf=0;mf<2;mf++) {
                int r = wm32 + mf*16 + g;
                a[mf][0] = As[r  ][j*8 + t];
                a[mf][1] = As[r+8][j*8 + t];
                a[mf][2] = As[r  ][j*8 + t + 4];
                a[mf][3] = As[r+8][j*8 + t + 4];
            }
            #pragma unroll
            for (int nf=0;nf<8;nf++) {
                int n = wn64 + nf*8 + g;
                uint32_t b0 = Bs[n][j*8 + t];
                uint32_t b1 = Bs[n][j*8 + t + 4];
                mma8(acc[0][nf], a[0], b0, b1);
                mma8(acc[1][nf], a[1], b0, b1);
            }
        }
        __syncthreads();
    }

    // epilogue
    #pragma unroll
    for (int mf=0;mf<2;mf++) {
        int m = bm + wm32 + mf*16 + g;
        #pragma unroll
        for (int nf=0;nf<8;nf++) {
            int n0 = bn + wn64 + nf*8 + 2*t;
            float bb0 = (n0   < Nreal) ? bias[n0]   : 0.f;
            float bb1 = (n0+1 < Nreal) ? bias[n0+1] : 0.f;
            float v0 = acc[mf][nf][0] + bb0;
            float v1 = acc[mf][nf][1] + bb1;
            float v2 = acc[mf][nf][2] + bb0;
            float v3 = acc[mf][nf][3] + bb1;
            if (doRelu) {
                v0=fmaxf(v0,0.f); v1=fmaxf(v1,0.f);
                v2=fmaxf(v2,0.f); v3=fmaxf(v3,0.f);
            }
            float2 lo = make_float2(v0, v1);
            float2 hi = make_float2(v2, v3);
            *(float2*)(C + (size_t)m*ldc + n0)     = lo;
            *(float2*)(C + (size_t)(m+8)*ldc + n0) = hi;
        }
    }
}

// ============================================================================
// LayerNorm + ReLU over rows of 1024. Block per row, 256 threads.
// ============================================================================
__global__ void ln_relu_kernel(const float* __restrict__ X, const float* __restrict__ g,
                               const float* __restrict__ beta, float* __restrict__ Y)
{
    int b = blockIdx.x, tid = threadIdx.x;
    const float* x = X + (size_t)b*TH;
    float* y = Y + (size_t)b*TH;
    float v[4], s = 0.f, s2 = 0.f;
    #pragma unroll
    for (int i=0;i<4;i++){ v[i]=x[tid + i*256]; s+=v[i]; s2+=v[i]*v[i]; }
    __shared__ float red[2][8];
    for (int o=16;o;o>>=1){ s += __shfl_xor_sync(0xffffffffu,s,o); s2 += __shfl_xor_sync(0xffffffffu,s2,o); }
    if ((tid&31)==0){ red[0][tid>>5]=s; red[1][tid>>5]=s2; }
    __syncthreads();
    float ts=0.f, ts2=0.f;
    #pragma unroll
    for (int w=0;w<8;w++){ ts+=red[0][w]; ts2+=red[1][w]; }
    float mean = ts*(1.f/TH);
    float var  = ts2*(1.f/TH) - mean*mean;
    float inv  = rsqrtf(var + 1e-5f);
    #pragma unroll
    for (int i=0;i<4;i++){
        int c = tid + i*256;
        float r = (v[i]-mean)*inv*g[c] + beta[c];
        y[c] = fmaxf(r, 0.f);
    }
}

// ============================================================================
// Dueling combine + softmax over atoms (padded inputs: val ld=128, adv ld=4224)
// ============================================================================
__global__ void combine_kernel(const float* __restrict__ val, const float* __restrict__ adv,
                               float* __restrict__ out)
{
    int b = blockIdx.x, tid = threadIdx.x;
    __shared__ float sadv[ADVN];
    __shared__ float sval[ATOMS];
    __shared__ float cmean[ATOMS];
    const float* arow = adv + (size_t)b*ADVP;
    for (int i = tid; i < ADVN; i += 256) sadv[i] = arow[i];
    if (tid < ATOMS) sval[tid] = val[(size_t)b*128 + tid];
    __syncthreads();
    if (tid < ATOMS) {
        float s = 0.f;
        for (int a = 0; a < ACTIONS; a++) s += sadv[a*ATOMS + tid];
        cmean[tid] = s * (1.f/ACTIONS);
    }
    __syncthreads();
    float* orow = out + (size_t)b*ADVN;
    for (int a = tid; a < ACTIONS; a += 256) {
        float q[ATOMS];
        float mx = -1e30f;
        #pragma unroll
        for (int t = 0; t < ATOMS; t++) {
            float qv = sval[t] + sadv[a*ATOMS+t] - cmean[t];
            q[t] = qv; mx = fmaxf(mx, qv);
        }
        float sum = 0.f;
        #pragma unroll
        for (int t = 0; t < ATOMS; t++) { float e = expf(q[t]-mx); q[t]=e; sum += e; }
        float inv = 1.f/sum;
        #pragma unroll
        for (int t = 0; t < ATOMS; t++) orow[a*ATOMS+t] = q[t]*inv;
    }
}

// ============================================================================
extern "C" void kernel_launch(void* const* d_in, const int* in_sizes, int n_in,
                              void* d_out, int out_size)
{
    const float* state = (const float*)d_in[0];
    const float* embW  = (const float*)d_in[1];
    const float* embB  = (const float*)d_in[2];
    const float* lng   = (const float*)d_in[3];
    const float* lnb   = (const float*)d_in[4];
    const float* cls   = (const float*)d_in[5];
    const float* ipW   = (const float*)d_in[6];
    const float* ipb   = (const float*)d_in[7];
    const float* opW   = (const float*)d_in[8];
    const float* opb   = (const float*)d_in[9];
    const float* t0W   = (const float*)d_in[10];
    const float* t0b   = (const float*)d_in[11];
    const float* t0g   = (const float*)d_in[12];
    const float* t0be  = (const float*)d_in[13];
    const float* t1W   = (const float*)d_in[14];
    const float* t1b   = (const float*)d_in[15];
    const float* t1g   = (const float*)d_in[16];
    const float* t1be  = (const float*)d_in[17];
    const float* vfW   = (const float*)d_in[18];
    const float* vfb   = (const float*)d_in[19];
    const float* voW   = (const float*)d_in[20];
    const float* vob   = (const float*)d_in[21];
    const float* afW   = (const float*)d_in[22];
    const float* afb   = (const float*)d_in[23];
    const float* aoW   = (const float*)d_in[24];
    const float* aob   = (const float*)d_in[25];
    float* out = (float*)d_out;

    float *tin, *pre, *h, *vfc, *afc, *valb, *advb;
    float *t0Wt, *t1Wt, *vfWt, *afWt, *voWt, *aoWt;
    cudaGetSymbolAddress((void**)&tin,  g_tin);
    cudaGetSymbolAddress((void**)&pre,  g_pre);
    cudaGetSymbolAddress((void**)&h,    g_h);
    cudaGetSymbolAddress((void**)&vfc,  g_vfc);
    cudaGetSymbolAddress((void**)&afc,  g_afc);
    cudaGetSymbolAddress((void**)&valb, g_val);
    cudaGetSymbolAddress((void**)&advb, g_adv);
    cudaGetSymbolAddress((void**)&t0Wt, g_t0Wt);
    cudaGetSymbolAddress((void**)&t1Wt, g_t1Wt);
    cudaGetSymbolAddress((void**)&vfWt, g_vfWt);
    cudaGetSymbolAddress((void**)&afWt, g_afWt);
    cudaGetSymbolAddress((void**)&voWt, g_voWt);
    cudaGetSymbolAddress((void**)&aoWt, g_aoWt);

    setup_kernel<<<1, 1024>>>(embW, embB, lng, lnb, cls, ipW, ipb, opW);
    front_kernel<<<BATCH, 128>>>(state, opb);

    dim3 tb(32, 8);
    transpose_pad_kernel<<<dim3(TIN_PAD/32, 1024/32), tb>>>(t0W, 1488, 1024, t0Wt, TIN_PAD);
    transpose_pad_kernel<<<dim3(1024/32,    1024/32), tb>>>(t1W, 1024, 1024, t1Wt, 1024);
    transpose_pad_kernel<<<dim3(1024/32,     512/32), tb>>>(vfW, 1024,  512, vfWt, 1024);
    transpose_pad_kernel<<<dim3(1024/32,     512/32), tb>>>(afW, 1024,  512, afWt, 1024);
    transpose_pad_kernel<<<dim3( 512/32,     128/32), tb>>>(voW,  512, ATOMS, voWt, 512);
    transpose_pad_kernel<<<dim3( 512/32,    ADVP/32), tb>>>(aoW,  512, ADVN, aoWt, 512);

    // t0: [8192,1536] @ [1536,1024]
    mma_gemm_kernel<<<dim3(1024/128, BATCH/128), 256>>>(
        TIN_PAD, tin, TIN_PAD, t0Wt, pre, TH, TH, t0b, 0);
    ln_relu_kernel<<<BATCH, 256>>>(pre, t0g, t0be, h);

    // t1
    mma_gemm_kernel<<<dim3(1024/128, BATCH/128), 256>>>(
        TH, h, TH, t1Wt, pre, TH, TH, t1b, 0);
    ln_relu_kernel<<<BATCH, 256>>>(pre, t1g, t1be, h);

    // value / advantage fc (relu)
    mma_gemm_kernel<<<dim3(512/128, BATCH/128), 256>>>(
        TH, h, TH, vfWt, vfc, 512, 512, vfb, 1);
    mma_gemm_kernel<<<dim3(512/128, BATCH/128), 256>>>(
        TH, h, TH, afWt, afc, 512, 512, afb, 1);

    // heads
    mma_gemm_kernel<<<dim3(128/128, BATCH/128), 256>>>(
        512, vfc, 512, voWt, valb, 128, ATOMS, vob, 0);
    mma_gemm_kernel<<<dim3(ADVP/128, BATCH/128), 256>>>(
        512, afc, 512, aoWt, advb, ADVP, ADVN, aob, 0);

    combine_kernel<<<BATCH, 256>>>(valb, advb, out);
}

// round 10
// speedup vs baseline: 5.3983x; 1.4387x over previous
#include <cuda_runtime.h>
#include <cuda_fp16.h>
#include <math.h>
#include <stdint.h>

#define BATCH   8192
#define STATE_N 1360
#define TIN_PAD 1536
#define TH      1024
#define ATOMS   51
#define ACTIONS 81
#define ADVN    (ACTIONS*ATOMS)   // 4131
#define ADVP    4224              // 33*128

// ------------------------- scratch (no cudaMalloc allowed) ------------------
__device__ __align__(16) __half g_tin[(size_t)BATCH*TIN_PAD];
__device__ __align__(16) float  g_pre[(size_t)BATCH*TH];
__device__ __align__(16) __half g_h  [(size_t)BATCH*TH];
__device__ __align__(16) __half g_vfc[(size_t)BATCH*512];
__device__ __align__(16) __half g_afc[(size_t)BATCH*512];
__device__ __align__(16) float  g_val[(size_t)BATCH*128];
__device__ __align__(16) float  g_adv[(size_t)BATCH*ADVP];
// transposed (K-major, padded) fp16 weights
__device__ __align__(16) __half g_t0Wt[(size_t)1024*TIN_PAD];
__device__ __align__(16) __half g_t1Wt[(size_t)1024*1024];
__device__ __align__(16) __half g_vfWt[(size_t)512*1024];
__device__ __align__(16) __half g_afWt[(size_t)512*1024];
__device__ __align__(16) __half g_voWt[(size_t)128*512];
__device__ __align__(16) __half g_aoWt[(size_t)ADVP*512];

// ------------------------- folded front-end operators -----------------------
__device__ float d_M[8*128];
__device__ float d_G[64];
__device__ float d_Mk[8*128];
__device__ float d_Mv[8*128];
__device__ float d_kb[128];
__device__ float d_vb[128];
__device__ float d_q0[128];
__device__ float d_kcls[128];
__device__ float d_vcls[128];
__device__ float d_A[32];
__device__ float d_Cc[4];
__device__ float d_sc0[4];
__device__ float d_Q[4096];
__device__ float d_P1[512];
__device__ float d_P2[512];

// ============================================================================
// Setup fold. One block, 1024 threads, batch-independent.
// ============================================================================
__global__ void setup_kernel(const float* __restrict__ embW, const float* __restrict__ embB,
                             const float* __restrict__ lng,  const float* __restrict__ lnb,
                             const float* __restrict__ cls,  const float* __restrict__ ipW,
                             const float* __restrict__ ipb,  const float* __restrict__ opW)
{
    int tid = threadIdx.x;
    __shared__ float em[8];
    if (tid < 8) {
        float s = 0.f;
        if (tid < 7) { for (int c=0;c<128;c++) s += embW[tid*128+c]; }
        else         { for (int c=0;c<128;c++) s += embB[c]; }
        em[tid] = s * (1.f/128.f);
    }
    __syncthreads();
    if (tid < 128) {
        int c = tid;
        for (int f=0; f<7; f++) d_M[f*128+c] = embW[f*128+c] - em[f];
        d_M[7*128+c] = embB[c] - em[7];
    }
    __syncthreads();
    if (tid < 64) {
        int i = tid>>3, j = tid&7;
        float s = 0.f;
        for (int c=0;c<128;c++) s += d_M[i*128+c]*d_M[j*128+c];
        d_G[tid] = s * (1.f/128.f);
    }
    const float* Wq = ipW;
    const float* Wk = ipW + 128*128;
    const float* Wv = ipW + 256*128;
    for (int idx=tid; idx<1024; idx+=1024) {
        int i = idx>>7, c2 = idx&127;
        float sk=0.f, sv=0.f;
        for (int c=0;c<128;c++) {
            float mg = d_M[i*128+c]*lng[c];
            sk += mg*Wk[c2*128+c];
            sv += mg*Wv[c2*128+c];
        }
        d_Mk[idx] = sk; d_Mv[idx] = sv;
    }
    if (tid < 128) {
        int c2 = tid;
        float sk=0.f, sv=0.f, sq=0.f, skc=0.f, svc=0.f;
        for (int c=0;c<128;c++) {
            float bl = lnb[c], cl = cls[c];
            sk  += bl*Wk[c2*128+c];
            sv  += bl*Wv[c2*128+c];
            sq  += cl*Wq[c2*128+c];
            skc += cl*Wk[c2*128+c];
            svc += cl*Wv[c2*128+c];
        }
        d_kb[c2]   = sk  + ipb[128+c2];
        d_vb[c2]   = sv  + ipb[256+c2];
        d_q0[c2]   = sq  + ipb[c2];
        d_kcls[c2] = skc + ipb[128+c2];
        d_vcls[c2] = svc + ipb[256+c2];
    }
    __syncthreads();
    const float inv_s32 = 0.17677669529663687f;
    if (tid < 32) {
        int h = tid>>3, i = tid&7;
        float s = 0.f;
        for (int u=0;u<32;u++) s += d_Mk[i*128 + h*32+u]*d_q0[h*32+u];
        d_A[tid] = s*inv_s32;
    }
    if (tid >= 32 && tid < 36) {
        int h = tid-32; float s = 0.f;
        for (int u=0;u<32;u++) s += d_kb[h*32+u]*d_q0[h*32+u];
        d_Cc[h] = s*inv_s32;
    }
    if (tid >= 36 && tid < 40) {
        int h = tid-36; float s = 0.f;
        for (int u=0;u<32;u++) s += d_kcls[h*32+u]*d_q0[h*32+u];
        d_sc0[h] = s*inv_s32;
    }
    __syncthreads();
    for (int idx=tid; idx<4096; idx+=1024) {
        int h = idx>>10, i = (idx>>7)&7, c = idx&127;
        float s = 0.f;
        for (int u=0;u<32;u++) s += d_Mv[i*128 + h*32+u]*opW[c*128 + h*32+u];
        d_Q[idx] = s;
    }
    for (int idx=tid; idx<512; idx+=1024) {
        int h = idx>>7, c = idx&127;
        float s1=0.f, s2=0.f;
        for (int u=0;u<32;u++) {
            float w = opW[c*128 + h*32+u];
            s1 += d_vcls[h*32+u]*w;
            s2 += d_vb  [h*32+u]*w;
        }
        d_P1[idx] = s1; d_P2[idx] = s2;
    }
}

// ============================================================================
// Front: collapsed attention -> pooled; copies state (fp16); pads K to 1536.
// ============================================================================
__global__ void front_kernel(const float* __restrict__ state, const float* __restrict__ opb)
{
    int b = blockIdx.x, tid = threadIdx.x;
    const float* srow = state + (size_t)b*STATE_N;
    __half* trow = g_tin + (size_t)b*TIN_PAD;
    for (int i=tid; i<STATE_N; i+=128) trow[i] = __float2half(srow[i]);
    if (tid < 48) trow[1488 + tid] = __float2half(0.f);

    __shared__ float tokp[68][8];
    __shared__ float s_s[68];
    __shared__ int   smask[68];
    __shared__ int   s_ae;
    __shared__ float sy[4][8];
    __shared__ float sa0[4];

    if (tid < 68) {
        const int defs[9]  = {16,8,4,4,4,8,8,8,8};
        const int bases[9] = {59,124,157,174,191,208,241,274,307};
        int t = tid, cat = 0, start = 0;
        while (t >= start + defs[cat]) { start += defs[cat]; cat++; }
        int slot = t - start;
        int lo = 1020 + bases[cat] + 1 + slot*4;
        int po =  680 + bases[cat] + 1 + slot*4;
        float pr = srow[lo+0], dx = srow[lo+1], dy = srow[lo+2], ds = srow[lo+3];
        float pp = srow[po+0], px = srow[po+1], py = srow[po+2];
        float vv = (pr > 0.5f && pp > 0.5f) ? 1.f : 0.f;
        float tk[8];
        tk[0]=dx; tk[1]=dy; tk[2]=ds; tk[3]=(dx-px)*vv; tk[4]=(dy-py)*vv;
        tk[5]=(float)cat*0.125f; tk[6]=pr; tk[7]=1.f;
        #pragma unroll
        for (int i=0;i<8;i++) tokp[tid][i]=tk[i];
        float v = 0.f;
        #pragma unroll
        for (int i=0;i<8;i++)
            #pragma unroll
            for (int j=0;j<8;j++) v += tk[i]*tk[j]*d_G[i*8+j];
        v = fmaxf(v, 0.f);
        s_s[tid]   = rsqrtf(v + 1e-5f);
        smask[tid] = (pr < 0.5f) ? 1 : 0;
    }
    __syncthreads();
    if (tid == 0) {
        int ae = 1;
        for (int t=0;t<68;t++) ae &= smask[t];
        s_ae = ae;
    }
    __syncthreads();

    int w = tid>>5, lane = tid&31;
    float Ah[8];
    #pragma unroll
    for (int i=0;i<8;i++) Ah[i]=d_A[w*8+i];
    float Ch = d_Cc[w];
    float c0 = d_sc0[w];
    int   ae = s_ae;

    int t0i = lane, t1i = lane+32, t2i = lane+64;
    bool v2 = (t2i < 68);
    auto score = [&](int t)->float {
        if (smask[t] && !ae) return -1e9f;
        float acc = 0.f;
        #pragma unroll
        for (int i=0;i<8;i++) acc += tokp[t][i]*Ah[i];
        return s_s[t]*acc + Ch;
    };
    float sA = score(t0i);
    float sB = score(t1i);
    float sC = v2 ? score(t2i) : -1e9f;
    float mx = fmaxf(fmaxf(sA,sB), fmaxf(sC, c0));
    for (int o=16;o;o>>=1) mx = fmaxf(mx, __shfl_xor_sync(0xffffffffu, mx, o));
    float eA = expf(sA-mx), eB = expf(sB-mx), eC = v2 ? expf(sC-mx) : 0.f;
    float ecls = expf(c0-mx);
    float ssum = eA+eB+eC;
    for (int o=16;o;o>>=1) ssum += __shfl_xor_sync(0xffffffffu, ssum, o);
    float inv = 1.f/(ssum + ecls);
    float wA = eA*s_s[t0i], wB = eB*s_s[t1i], wC = v2 ? eC*s_s[t2i] : 0.f;
    #pragma unroll
    for (int i=0;i<8;i++) {
        float yy = wA*tokp[t0i][i] + wB*tokp[t1i][i];
        if (v2) yy += wC*tokp[t2i][i];
        for (int o=16;o;o>>=1) yy += __shfl_xor_sync(0xffffffffu, yy, o);
        if (lane==0) sy[w][i] = yy*inv;
    }
    if (lane==0) sa0[w] = ecls*inv;
    __syncthreads();

    {
        int c = tid;
        float acc = opb[c];
        #pragma unroll
        for (int h=0;h<4;h++) {
            float a0 = sa0[h];
            acc += a0*d_P1[h*128+c] + (1.f-a0)*d_P2[h*128+c];
            #pragma unroll
            for (int i=0;i<8;i++) acc += sy[h][i]*d_Q[(h*8+i)*128 + c];
        }
        trow[STATE_N + c] = __float2half(acc);
    }
}

// ============================================================================
// Transpose + pad: W[K][N] fp32 -> Wt[NP][KP] fp16 (K-major rows, zero pad)
// ============================================================================
__global__ void transpose_pad_kernel(const float* __restrict__ W, int K, int N,
                                     __half* __restrict__ Wt, int KP)
{
    __shared__ float t[32][33];
    int k0 = blockIdx.x*32, n0 = blockIdx.y*32;
    for (int i = threadIdx.y; i < 32; i += 8) {
        int k = k0 + i, n = n0 + threadIdx.x;
        t[i][threadIdx.x] = (k < K && n < N) ? W[(size_t)k*N + n] : 0.f;
    }
    __syncthreads();
    for (int i = threadIdx.y; i < 32; i += 8) {
        int n = n0 + i, k = k0 + threadIdx.x;
        Wt[(size_t)n*KP + k] = __float2half(t[threadIdx.x][i]);
    }
}

// ============================================================================
// fp16 mma.sync GEMM: C[M,NP] = A[M,K] @ Bt[NP,K]^T + bias (opt relu)
// block 128x128, BK=32, 256 threads (8 warps, 4m x 2n), warp tile 32x64.
// mma.sync.m16n8k16 f16 in, f32 accum. cp.async 3-stage pipeline.
// K%32==0, M%128==0, NP%128==0.
// ============================================================================
#define SROW 20                     // words per smem row (16 data + 4 pad)
#define STGW (128*SROW)             // words per operand per stage
#define HSMEM_BYTES (3*2*STGW*4)    // 61440

__device__ __forceinline__ uint32_t smem_u32(const void* p) {
    uint32_t a;
    asm("{ .reg .u64 t; cvta.to.shared.u64 t, %1; cvt.u32.u64 %0, t; }" : "=r"(a) : "l"(p));
    return a;
}
__device__ __forceinline__ void cp16(uint32_t s, const void* g) {
    asm volatile("cp.async.cg.shared.global [%0], [%1], 16;" :: "r"(s), "l"(g));
}
#define CP_COMMIT() asm volatile("cp.async.commit_group;" ::: "memory")
#define CP_WAIT1()  asm volatile("cp.async.wait_group 1;" ::: "memory")

__device__ __forceinline__ void mma16(float* c, const uint32_t* a, uint32_t b0, uint32_t b1) {
    asm volatile("mma.sync.aligned.m16n8k16.row.col.f32.f16.f16.f32 "
        "{%0,%1,%2,%3}, {%4,%5,%6,%7}, {%8,%9}, {%0,%1,%2,%3};"
        : "+f"(c[0]), "+f"(c[1]), "+f"(c[2]), "+f"(c[3])
        : "r"(a[0]), "r"(a[1]), "r"(a[2]), "r"(a[3]), "r"(b0), "r"(b1));
}

__global__ __launch_bounds__(256, 2)
void hgemm_kernel(int K, const __half* __restrict__ A, int lda,
                  const __half* __restrict__ Bt,
                  void* __restrict__ Cv, int ldc, int Nreal,
                  const float* __restrict__ bias, int doRelu, int outHalf)
{
    extern __shared__ __align__(16) uint32_t smw[];
    int tid = threadIdx.x;
    int wid = tid >> 5, lane = tid & 31;
    int g = lane >> 2, t = lane & 3;
    int wm = (wid & 3) * 32;
    int wn = (wid >> 2) * 64;
    int bm = blockIdx.y * 128, bn = blockIdx.x * 128;

    uint32_t sbase = smem_u32(smw);
    // chunk mapping: 512 16B chunks per operand per stage, 2 per thread
    int r0 = tid >> 2, c0 = (tid & 3);   // rows 0..63
    int r1 = r0 + 64;                    // rows 64..127
    const __half* Ag0 = A  + (size_t)(bm + r0)*lda + c0*8;
    const __half* Ag1 = A  + (size_t)(bm + r1)*lda + c0*8;
    const __half* Bg0 = Bt + (size_t)(bn + r0)*K   + c0*8;
    const __half* Bg1 = Bt + (size_t)(bn + r1)*K   + c0*8;
    uint32_t wA0 = (uint32_t)(r0*SROW + c0*4)*4;
    uint32_t wA1 = (uint32_t)(r1*SROW + c0*4)*4;

    float acc[2][8][4];
    #pragma unroll
    for (int mf=0;mf<2;mf++)
        #pragma unroll
        for (int nf=0;nf<8;nf++)
            #pragma unroll
            for (int e=0;e<4;e++) acc[mf][nf][e]=0.f;

    int nst = K >> 5;
    // preload stages 0,1
    #pragma unroll
    for (int p = 0; p < 2; p++) {
        uint32_t sa = sbase + (uint32_t)(p*2*STGW)*4;
        uint32_t sb = sa + STGW*4;
        size_t k0 = (size_t)p*32;
        cp16(sa + wA0, Ag0 + k0);
        cp16(sa + wA1, Ag1 + k0);
        cp16(sb + wA0, Bg0 + k0);
        cp16(sb + wA1, Bg1 + k0);
        CP_COMMIT();
    }

    for (int s = 0; s < nst; s++) {
        int st = s % 3;
        const uint32_t* sa = smw + st*2*STGW;
        const uint32_t* sb = sa + STGW;
        CP_WAIT1();
        __syncthreads();
        #pragma unroll
        for (int j = 0; j < 2; j++) {
            uint32_t a[2][4];
            #pragma unroll
            for (int mf=0;mf<2;mf++) {
                int r = wm + mf*16 + g;
                a[mf][0] = sa[r*SROW + j*8 + t];
                a[mf][1] = sa[(r+8)*SROW + j*8 + t];
                a[mf][2] = sa[r*SROW + j*8 + t + 4];
                a[mf][3] = sa[(r+8)*SROW + j*8 + t + 4];
            }
            #pragma unroll
            for (int nf=0;nf<8;nf++) {
                int n = wn + nf*8 + g;
                uint32_t b0 = sb[n*SROW + j*8 + t];
                uint32_t b1 = sb[n*SROW + j*8 + t + 4];
                mma16(acc[0][nf], a[0], b0, b1);
                mma16(acc[1][nf], a[1], b0, b1);
            }
        }
        // issue stage s+2 (into buffer (s+2)%3, freed by the barrier above)
        if (s + 2 < nst) {
            int sn = (s + 2) % 3;
            uint32_t na = sbase + (uint32_t)(sn*2*STGW)*4;
            uint32_t nb = na + STGW*4;
            size_t k0 = (size_t)(s + 2)*32;
            cp16(na + wA0, Ag0 + k0);
            cp16(na + wA1, Ag1 + k0);
            cp16(nb + wA0, Bg0 + k0);
            cp16(nb + wA1, Bg1 + k0);
        }
        CP_COMMIT();
    }

    // epilogue: lane (g,t); c0,c1 -> row g, cols 2t,2t+1; c2,c3 -> row g+8
    #pragma unroll
    for (int mf=0;mf<2;mf++) {
        int m = bm + wm + mf*16 + g;
        #pragma unroll
        for (int nf=0;nf<8;nf++) {
            int n0 = bn + wn + nf*8 + 2*t;
            float bb0 = (n0   < Nreal) ? bias[n0]   : 0.f;
            float bb1 = (n0+1 < Nreal) ? bias[n0+1] : 0.f;
            float v0 = acc[mf][nf][0] + bb0;
            float v1 = acc[mf][nf][1] + bb1;
            float v2 = acc[mf][nf][2] + bb0;
            float v3 = acc[mf][nf][3] + bb1;
            if (doRelu) {
                v0=fmaxf(v0,0.f); v1=fmaxf(v1,0.f);
                v2=fmaxf(v2,0.f); v3=fmaxf(v3,0.f);
            }
            if (outHalf) {
                __half2* C = (__half2*)Cv;
                C[((size_t)m*ldc + n0) >> 1]     = __floats2half2_rn(v0, v1);
                C[((size_t)(m+8)*ldc + n0) >> 1] = __floats2half2_rn(v2, v3);
            } else {
                float* C = (float*)Cv;
                *(float2*)(C + (size_t)m*ldc + n0)     = make_float2(v0, v1);
                *(float2*)(C + (size_t)(m+8)*ldc + n0) = make_float2(v2, v3);
            }
        }
    }
}

// ============================================================================
// LayerNorm + ReLU over rows of 1024: fp32 in, fp16 out.
// ============================================================================
__global__ void ln_relu_kernel(const float* __restrict__ X, const float* __restrict__ g,
                               const float* __restrict__ beta, __half* __restrict__ Y)
{
    int b = blockIdx.x, tid = threadIdx.x;
    const float* x = X + (size_t)b*TH;
    __half* y = Y + (size_t)b*TH;
    float v[4], s = 0.f, s2 = 0.f;
    #pragma unroll
    for (int i=0;i<4;i++){ v[i]=x[tid + i*256]; s+=v[i]; s2+=v[i]*v[i]; }
    __shared__ float red[2][8];
    for (int o=16;o;o>>=1){ s += __shfl_xor_sync(0xffffffffu,s,o); s2 += __shfl_xor_sync(0xffffffffu,s2,o); }
    if ((tid&31)==0){ red[0][tid>>5]=s; red[1][tid>>5]=s2; }
    __syncthreads();
    float ts=0.f, ts2=0.f;
    #pragma unroll
    for (int w=0;w<8;w++){ ts+=red[0][w]; ts2+=red[1][w]; }
    float mean = ts*(1.f/TH);
    float var  = ts2*(1.f/TH) - mean*mean;
    float inv  = rsqrtf(var + 1e-5f);
    #pragma unroll
    for (int i=0;i<4;i++){
        int c = tid + i*256;
        float r = (v[i]-mean)*inv*g[c] + beta[c];
        y[c] = __float2half(fmaxf(r, 0.f));
    }
}

// ============================================================================
// Dueling combine + softmax over atoms (val ld=128 fp32, adv ld=4224 fp32)
// ============================================================================
__global__ void combine_kernel(const float* __restrict__ val, const float* __restrict__ adv,
                               float* __restrict__ out)
{
    int b = blockIdx.x, tid = threadIdx.x;
    __shared__ float sadv[ADVN];
    __shared__ float sval[ATOMS];
    __shared__ float cmean[ATOMS];
    const float* arow = adv + (size_t)b*ADVP;
    for (int i = tid; i < ADVN; i += 256) sadv[i] = arow[i];
    if (tid < ATOMS) sval[tid] = val[(size_t)b*128 + tid];
    __syncthreads();
    if (tid < ATOMS) {
        float s = 0.f;
        for (int a = 0; a < ACTIONS; a++) s += sadv[a*ATOMS + tid];
        cmean[tid] = s * (1.f/ACTIONS);
    }
    __syncthreads();
    float* orow = out + (size_t)b*ADVN;
    for (int a = tid; a < ACTIONS; a += 256) {
        float q[ATOMS];
        float mx = -1e30f;
        #pragma unroll
        for (int t = 0; t < ATOMS; t++) {
            float qv = sval[t] + sadv[a*ATOMS+t] - cmean[t];
            q[t] = qv; mx = fmaxf(mx, qv);
        }
        float sum = 0.f;
        #pragma unroll
        for (int t = 0; t < ATOMS; t++) { float e = expf(q[t]-mx); q[t]=e; sum += e; }
        float inv = 1.f/sum;
        #pragma unroll
        for (int t = 0; t < ATOMS; t++) orow[a*ATOMS+t] = q[t]*inv;
    }
}

// ============================================================================
extern "C" void kernel_launch(void* const* d_in, const int* in_sizes, int n_in,
                              void* d_out, int out_size)
{
    const float* state = (const float*)d_in[0];
    const float* embW  = (const float*)d_in[1];
    const float* embB  = (const float*)d_in[2];
    const float* lng   = (const float*)d_in[3];
    const float* lnb   = (const float*)d_in[4];
    const float* cls   = (const float*)d_in[5];
    const float* ipW   = (const float*)d_in[6];
    const float* ipb   = (const float*)d_in[7];
    const float* opW   = (const float*)d_in[8];
    const float* opb   = (const float*)d_in[9];
    const float* t0W   = (const float*)d_in[10];
    const float* t0b   = (const float*)d_in[11];
    const float* t0g   = (const float*)d_in[12];
    const float* t0be  = (const float*)d_in[13];
    const float* t1W   = (const float*)d_in[14];
    const float* t1b   = (const float*)d_in[15];
    const float* t1g   = (const float*)d_in[16];
    const float* t1be  = (const float*)d_in[17];
    const float* vfW   = (const float*)d_in[18];
    const float* vfb   = (const float*)d_in[19];
    const float* voW   = (const float*)d_in[20];
    const float* vob   = (const float*)d_in[21];
    const float* afW   = (const float*)d_in[22];
    const float* afb   = (const float*)d_in[23];
    const float* aoW   = (const float*)d_in[24];
    const float* aob   = (const float*)d_in[25];
    float* out = (float*)d_out;

    __half *tin, *h, *vfc, *afc;
    float *pre, *valb, *advb;
    __half *t0Wt, *t1Wt, *vfWt, *afWt, *voWt, *aoWt;
    cudaGetSymbolAddress((void**)&tin,  g_tin);
    cudaGetSymbolAddress((void**)&pre,  g_pre);
    cudaGetSymbolAddress((void**)&h,    g_h);
    cudaGetSymbolAddress((void**)&vfc,  g_vfc);
    cudaGetSymbolAddress((void**)&afc,  g_afc);
    cudaGetSymbolAddress((void**)&valb, g_val);
    cudaGetSymbolAddress((void**)&advb, g_adv);
    cudaGetSymbolAddress((void**)&t0Wt, g_t0Wt);
    cudaGetSymbolAddress((void**)&t1Wt, g_t1Wt);
    cudaGetSymbolAddress((void**)&vfWt, g_vfWt);
    cudaGetSymbolAddress((void**)&afWt, g_afWt);
    cudaGetSymbolAddress((void**)&voWt, g_voWt);
    cudaGetSymbolAddress((void**)&aoWt, g_aoWt);

    cudaFuncSetAttribute(hgemm_kernel,
                         cudaFuncAttributeMaxDynamicSharedMemorySize, HSMEM_BYTES);

    setup_kernel<<<1, 1024>>>(embW, embB, lng, lnb, cls, ipW, ipb, opW);
    front_kernel<<<BATCH, 128>>>(state, opb);

    dim3 tb(32, 8);
    transpose_pad_kernel<<<dim3(TIN_PAD/32, 1024/32), tb>>>(t0W, 1488, 1024, t0Wt, TIN_PAD);
    transpose_pad_kernel<<<dim3(1024/32,    1024/32), tb>>>(t1W, 1024, 1024, t1Wt, 1024);
    transpose_pad_kernel<<<dim3(1024/32,     512/32), tb>>>(vfW, 1024,  512, vfWt, 1024);
    transpose_pad_kernel<<<dim3(1024/32,     512/32), tb>>>(afW, 1024,  512, afWt, 1024);
    transpose_pad_kernel<<<dim3( 512/32,     128/32), tb>>>(voW,  512, ATOMS, voWt, 512);
    transpose_pad_kernel<<<dim3( 512/32,    ADVP/32), tb>>>(aoW,  512, ADVN, aoWt, 512);

    // t0: [8192,1536] @ [1536,1024] -> fp32 pre
    hgemm_kernel<<<dim3(1024/128, BATCH/128), 256, HSMEM_BYTES>>>(
        TIN_PAD, tin, TIN_PAD, t0Wt, pre, TH, TH, t0b, 0, 0);
    ln_relu_kernel<<<BATCH, 256>>>(pre, t0g, t0be, h);

    // t1
    hgemm_kernel<<<dim3(1024/128, BATCH/128), 256, HSMEM_BYTES>>>(
        TH, h, TH, t1Wt, pre, TH, TH, t1b, 0, 0);
    ln_relu_kernel<<<BATCH, 256>>>(pre, t1g, t1be, h);

    // value / advantage fc (relu, fp16 out)
    hgemm_kernel<<<dim3(512/128, BATCH/128), 256, HSMEM_BYTES>>>(
        TH, h, TH, vfWt, vfc, 512, 512, vfb, 1, 1);
    hgemm_kernel<<<dim3(512/128, BATCH/128), 256, HSMEM_BYTES>>>(
        TH, h, TH, afWt, afc, 512, 512, afb, 1, 1);

    // heads (fp32 out)
    hgemm_kernel<<<dim3(128/128, BATCH/128), 256, HSMEM_BYTES>>>(
        512, vfc, 512, voWt, valb, 128, ATOMS, vob, 0, 0);
    hgemm_kernel<<<dim3(ADVP/128, BATCH/128), 256, HSMEM_BYTES>>>(
        512, afc, 512, aoWt, advb, ADVP, ADVN, aob, 0, 0);

    combine_kernel<<<BATCH, 256>>>(valb, advb, out);
}

// round 11
// speedup vs baseline: 5.4595x; 1.0113x over previous
#include <cuda_runtime.h>
#include <cuda_fp16.h>
#include <math.h>
#include <stdint.h>

#define BATCH   8192
#define STATE_N 1360
#define TIN_PAD 1536
#define TH      1024
#define ATOMS   51
#define ACTIONS 81
#define ADVN    (ACTIONS*ATOMS)   // 4131
#define ADVP    4224              // 33*128

// ------------------------- scratch (no cudaMalloc allowed) ------------------
__device__ __align__(16) __half g_tin[(size_t)BATCH*TIN_PAD];
__device__ __align__(16) float  g_pre[(size_t)BATCH*TH];
__device__ __align__(16) __half g_h  [(size_t)BATCH*TH];
__device__ __align__(16) __half g_vfc[(size_t)BATCH*512];
__device__ __align__(16) __half g_afc[(size_t)BATCH*512];
__device__ __align__(16) float  g_val[(size_t)BATCH*128];
__device__ __align__(16) float  g_adv[(size_t)BATCH*ADVP];
// transposed (K-major, padded) fp16 weights
__device__ __align__(16) __half g_t0Wt[(size_t)1024*TIN_PAD];
__device__ __align__(16) __half g_t1Wt[(size_t)1024*1024];
__device__ __align__(16) __half g_vfWt[(size_t)512*1024];
__device__ __align__(16) __half g_afWt[(size_t)512*1024];
__device__ __align__(16) __half g_voWt[(size_t)128*512];
__device__ __align__(16) __half g_aoWt[(size_t)ADVP*512];

// ------------------------- folded front-end operators -----------------------
__device__ float d_M[8*128];
__device__ float d_G[64];
__device__ float d_Mk[8*128];
__device__ float d_Mv[8*128];
__device__ float d_kb[128];
__device__ float d_vb[128];
__device__ float d_q0[128];
__device__ float d_kcls[128];
__device__ float d_vcls[128];
__device__ float d_A[32];
__device__ float d_Cc[4];
__device__ float d_sc0[4];
__device__ float d_Q[4096];
__device__ float d_P1[512];
__device__ float d_P2[512];

// ============================================================================
// Fast exp on the FMA pipe (valid for x <= 0; clamps at -80).
// ============================================================================
__device__ __forceinline__ float fexp(float x) {
    x = fmaxf(x, -80.f);
    const float L2E = 1.4426950408889634f;
    float y = fmaf(x, L2E, 12582912.0f);          // round(x*log2e) in mantissa
    int   iy = __float_as_int(y);
    float n  = y - 12582912.0f;
    float f  = fmaf(x, L2E, -n);                  // frac in [-0.5, 0.5]
    float p  = 1.33333605e-3f;
    p = fmaf(p, f, 9.61812910e-3f);
    p = fmaf(p, f, 5.55041086e-2f);
    p = fmaf(p, f, 2.40226507e-1f);
    p = fmaf(p, f, 6.93147181e-1f);
    p = fmaf(p, f, 1.0f);
    float s = __int_as_float((iy - 0x4B400000 + 127) << 23);   // 2^n
    return p * s;
}

// ============================================================================
// Setup fold. One block, 1024 threads, batch-independent.
// ============================================================================
__global__ void setup_kernel(const float* __restrict__ embW, const float* __restrict__ embB,
                             const float* __restrict__ lng,  const float* __restrict__ lnb,
                             const float* __restrict__ cls,  const float* __restrict__ ipW,
                             const float* __restrict__ ipb,  const float* __restrict__ opW)
{
    int tid = threadIdx.x;
    __shared__ float em[8];
    if (tid < 8) {
        float s = 0.f;
        if (tid < 7) { for (int c=0;c<128;c++) s += embW[tid*128+c]; }
        else         { for (int c=0;c<128;c++) s += embB[c]; }
        em[tid] = s * (1.f/128.f);
    }
    __syncthreads();
    if (tid < 128) {
        int c = tid;
        for (int f=0; f<7; f++) d_M[f*128+c] = embW[f*128+c] - em[f];
        d_M[7*128+c] = embB[c] - em[7];
    }
    __syncthreads();
    if (tid < 64) {
        int i = tid>>3, j = tid&7;
        float s = 0.f;
        for (int c=0;c<128;c++) s += d_M[i*128+c]*d_M[j*128+c];
        d_G[tid] = s * (1.f/128.f);
    }
    const float* Wq = ipW;
    const float* Wk = ipW + 128*128;
    const float* Wv = ipW + 256*128;
    for (int idx=tid; idx<1024; idx+=1024) {
        int i = idx>>7, c2 = idx&127;
        float sk=0.f, sv=0.f;
        for (int c=0;c<128;c++) {
            float mg = d_M[i*128+c]*lng[c];
            sk += mg*Wk[c2*128+c];
            sv += mg*Wv[c2*128+c];
        }
        d_Mk[idx] = sk; d_Mv[idx] = sv;
    }
    if (tid < 128) {
        int c2 = tid;
        float sk=0.f, sv=0.f, sq=0.f, skc=0.f, svc=0.f;
        for (int c=0;c<128;c++) {
            float bl = lnb[c], cl = cls[c];
            sk  += bl*Wk[c2*128+c];
            sv  += bl*Wv[c2*128+c];
            sq  += cl*Wq[c2*128+c];
            skc += cl*Wk[c2*128+c];
            svc += cl*Wv[c2*128+c];
        }
        d_kb[c2]   = sk  + ipb[128+c2];
        d_vb[c2]   = sv  + ipb[256+c2];
        d_q0[c2]   = sq  + ipb[c2];
        d_kcls[c2] = skc + ipb[128+c2];
        d_vcls[c2] = svc + ipb[256+c2];
    }
    __syncthreads();
    const float inv_s32 = 0.17677669529663687f;
    if (tid < 32) {
        int h = tid>>3, i = tid&7;
        float s = 0.f;
        for (int u=0;u<32;u++) s += d_Mk[i*128 + h*32+u]*d_q0[h*32+u];
        d_A[tid] = s*inv_s32;
    }
    if (tid >= 32 && tid < 36) {
        int h = tid-32; float s = 0.f;
        for (int u=0;u<32;u++) s += d_kb[h*32+u]*d_q0[h*32+u];
        d_Cc[h] = s*inv_s32;
    }
    if (tid >= 36 && tid < 40) {
        int h = tid-36; float s = 0.f;
        for (int u=0;u<32;u++) s += d_kcls[h*32+u]*d_q0[h*32+u];
        d_sc0[h] = s*inv_s32;
    }
    __syncthreads();
    for (int idx=tid; idx<4096; idx+=1024) {
        int h = idx>>10, i = (idx>>7)&7, c = idx&127;
        float s = 0.f;
        for (int u=0;u<32;u++) s += d_Mv[i*128 + h*32+u]*opW[c*128 + h*32+u];
        d_Q[idx] = s;
    }
    for (int idx=tid; idx<512; idx+=1024) {
        int h = idx>>7, c = idx&127;
        float s1=0.f, s2=0.f;
        for (int u=0;u<32;u++) {
            float w = opW[c*128 + h*32+u];
            s1 += d_vcls[h*32+u]*w;
            s2 += d_vb  [h*32+u]*w;
        }
        d_P1[idx] = s1; d_P2[idx] = s2;
    }
}

// ============================================================================
// Front: collapsed attention -> pooled; copies state (fp16); pads K to 1536.
// ============================================================================
__global__ void front_kernel(const float* __restrict__ state, const float* __restrict__ opb)
{
    int b = blockIdx.x, tid = threadIdx.x;
    const float* srow = state + (size_t)b*STATE_N;
    __half* trow = g_tin + (size_t)b*TIN_PAD;
    for (int i=tid; i<STATE_N; i+=128) trow[i] = __float2half(srow[i]);
    if (tid < 48) trow[1488 + tid] = __float2half(0.f);

    __shared__ float tokp[68][8];
    __shared__ float s_s[68];
    __shared__ int   smask[68];
    __shared__ int   s_ae;
    __shared__ float sy[4][8];
    __shared__ float sa0[4];

    if (tid < 68) {
        const int defs[9]  = {16,8,4,4,4,8,8,8,8};
        const int bases[9] = {59,124,157,174,191,208,241,274,307};
        int t = tid, cat = 0, start = 0;
        while (t >= start + defs[cat]) { start += defs[cat]; cat++; }
        int slot = t - start;
        int lo = 1020 + bases[cat] + 1 + slot*4;
        int po =  680 + bases[cat] + 1 + slot*4;
        float pr = srow[lo+0], dx = srow[lo+1], dy = srow[lo+2], ds = srow[lo+3];
        float pp = srow[po+0], px = srow[po+1], py = srow[po+2];
        float vv = (pr > 0.5f && pp > 0.5f) ? 1.f : 0.f;
        float tk[8];
        tk[0]=dx; tk[1]=dy; tk[2]=ds; tk[3]=(dx-px)*vv; tk[4]=(dy-py)*vv;
        tk[5]=(float)cat*0.125f; tk[6]=pr; tk[7]=1.f;
        #pragma unroll
        for (int i=0;i<8;i++) tokp[tid][i]=tk[i];
        float v = 0.f;
        #pragma unroll
        for (int i=0;i<8;i++)
            #pragma unroll
            for (int j=0;j<8;j++) v += tk[i]*tk[j]*d_G[i*8+j];
        v = fmaxf(v, 0.f);
        s_s[tid]   = rsqrtf(v + 1e-5f);
        smask[tid] = (pr < 0.5f) ? 1 : 0;
    }
    __syncthreads();
    if (tid == 0) {
        int ae = 1;
        for (int t=0;t<68;t++) ae &= smask[t];
        s_ae = ae;
    }
    __syncthreads();

    int w = tid>>5, lane = tid&31;
    float Ah[8];
    #pragma unroll
    for (int i=0;i<8;i++) Ah[i]=d_A[w*8+i];
    float Ch = d_Cc[w];
    float c0 = d_sc0[w];
    int   ae = s_ae;

    int t0i = lane, t1i = lane+32, t2i = lane+64;
    bool v2 = (t2i < 68);
    auto score = [&](int t)->float {
        if (smask[t] && !ae) return -1e9f;
        float acc = 0.f;
        #pragma unroll
        for (int i=0;i<8;i++) acc += tokp[t][i]*Ah[i];
        return s_s[t]*acc + Ch;
    };
    float sA = score(t0i);
    float sB = score(t1i);
    float sC = v2 ? score(t2i) : -1e9f;
    float mx = fmaxf(fmaxf(sA,sB), fmaxf(sC, c0));
    for (int o=16;o;o>>=1) mx = fmaxf(mx, __shfl_xor_sync(0xffffffffu, mx, o));
    float eA = fexp(sA-mx), eB = fexp(sB-mx), eC = v2 ? fexp(sC-mx) : 0.f;
    float ecls = fexp(c0-mx);
    float ssum = eA+eB+eC;
    for (int o=16;o;o>>=1) ssum += __shfl_xor_sync(0xffffffffu, ssum, o);
    float inv = 1.f/(ssum + ecls);
    float wA = eA*s_s[t0i], wB = eB*s_s[t1i], wC = v2 ? eC*s_s[t2i] : 0.f;
    #pragma unroll
    for (int i=0;i<8;i++) {
        float yy = wA*tokp[t0i][i] + wB*tokp[t1i][i];
        if (v2) yy += wC*tokp[t2i][i];
        for (int o=16;o;o>>=1) yy += __shfl_xor_sync(0xffffffffu, yy, o);
        if (lane==0) sy[w][i] = yy*inv;
    }
    if (lane==0) sa0[w] = ecls*inv;
    __syncthreads();

    {
        int c = tid;
        float acc = opb[c];
        #pragma unroll
        for (int h=0;h<4;h++) {
            float a0 = sa0[h];
            acc += a0*d_P1[h*128+c] + (1.f-a0)*d_P2[h*128+c];
            #pragma unroll
            for (int i=0;i<8;i++) acc += sy[h][i]*d_Q[(h*8+i)*128 + c];
        }
        trow[STATE_N + c] = __float2half(acc);
    }
}

// ============================================================================
// Transpose + pad: W[K][N] fp32 -> Wt[NP][KP] fp16 (K-major rows, zero pad)
// ============================================================================
__global__ void transpose_pad_kernel(const float* __restrict__ W, int K, int N,
                                     __half* __restrict__ Wt, int KP)
{
    __shared__ float t[32][33];
    int k0 = blockIdx.x*32, n0 = blockIdx.y*32;
    for (int i = threadIdx.y; i < 32; i += 8) {
        int k = k0 + i, n = n0 + threadIdx.x;
        t[i][threadIdx.x] = (k < K && n < N) ? W[(size_t)k*N + n] : 0.f;
    }
    __syncthreads();
    for (int i = threadIdx.y; i < 32; i += 8) {
        int n = n0 + i, k = k0 + threadIdx.x;
        Wt[(size_t)n*KP + k] = __float2half(t[threadIdx.x][i]);
    }
}

// ============================================================================
// fp16 mma.sync GEMM with ldmatrix + XOR-swizzled smem.
// block 128x128, BK=32, 256 threads (8 warps, 4m x 2n), warp tile 32x64.
// mma.sync.m16n8k16 f16 in, f32 accum. cp.async 3-stage pipeline.
// K%32==0, M%128==0, NP%128==0.
// Smem layout per operand tile (128 rows x 32 halves): line = r>>1 (128B),
// 16B chunk index phys = (((r&1)<<2)|c) ^ (line&7), c = k8-group (0..3).
// ============================================================================
#define ASTG 8192
#define STG_BYTES 16384

__device__ __forceinline__ uint32_t smem_u32(const void* p) {
    uint32_t a;
    asm("{ .reg .u64 t; cvta.to.shared.u64 t, %1; cvt.u32.u64 %0, t; }" : "=r"(a) : "l"(p));
    return a;
}
__device__ __forceinline__ void cp16(uint32_t s, const void* g) {
    asm volatile("cp.async.cg.shared.global [%0], [%1], 16;" :: "r"(s), "l"(g));
}
#define CP_COMMIT() asm volatile("cp.async.commit_group;" ::: "memory")
#define CP_WAIT1()  asm volatile("cp.async.wait_group 1;" ::: "memory")

__device__ __forceinline__ uint32_t soff(int r, int c) {
    int line = r >> 1;
    int v = ((r & 1) << 2) | c;
    return (uint32_t)(line*128 + ((v ^ (line & 7)) << 4));
}
__device__ __forceinline__ void ldm4(uint32_t* q, uint32_t addr) {
    asm volatile("ldmatrix.sync.aligned.m8n8.x4.shared.b16 {%0,%1,%2,%3}, [%4];"
        : "=r"(q[0]), "=r"(q[1]), "=r"(q[2]), "=r"(q[3]) : "r"(addr));
}
__device__ __forceinline__ void mma16(float* c, const uint32_t* a, uint32_t b0, uint32_t b1) {
    asm volatile("mma.sync.aligned.m16n8k16.row.col.f32.f16.f16.f32 "
        "{%0,%1,%2,%3}, {%4,%5,%6,%7}, {%8,%9}, {%0,%1,%2,%3};"
        : "+f"(c[0]), "+f"(c[1]), "+f"(c[2]), "+f"(c[3])
        : "r"(a[0]), "r"(a[1]), "r"(a[2]), "r"(a[3]), "r"(b0), "r"(b1));
}

__global__ __launch_bounds__(256, 2)
void hgemm_kernel(int K, const __half* __restrict__ A, int lda,
                  const __half* __restrict__ Bt,
                  void* __restrict__ Cv, int ldc, int Nreal,
                  const float* __restrict__ bias, int doRelu, int outHalf)
{
    __shared__ __align__(128) uint8_t smem[3*STG_BYTES];
    int tid = threadIdx.x;
    int wid = tid >> 5, lane = tid & 31;
    int g = lane >> 2, t = lane & 3;
    int wm = (wid & 3) * 32;
    int wn = (wid >> 2) * 64;
    int bm = blockIdx.y * 128, bn = blockIdx.x * 128;

    uint32_t sbase = smem_u32(smem);
    // cp.async mapping: thread -> rows r0, r0+64, k-chunk c0
    int r0 = tid >> 2, c0 = tid & 3;
    int r1 = r0 + 64;
    const __half* Ag0 = A  + (size_t)(bm + r0)*lda + c0*8;
    const __half* Ag1 = A  + (size_t)(bm + r1)*lda + c0*8;
    const __half* Bg0 = Bt + (size_t)(bn + r0)*K   + c0*8;
    const __half* Bg1 = Bt + (size_t)(bn + r1)*K   + c0*8;
    uint32_t wA0 = soff(r0, c0), wA1 = soff(r1, c0);

    // ldmatrix per-lane offsets (j=0; j=1 == XOR 32)
    int lr = lane & 15, lh = lane >> 4;
    uint32_t aoff[2], boff[4];
    #pragma unroll
    for (int mf = 0; mf < 2; mf++) aoff[mf] = soff(wm + mf*16 + lr, lh);
    #pragma unroll
    for (int nt = 0; nt < 4; nt++) boff[nt] = ASTG + soff(wn + nt*16 + lr, lh);

    float acc[2][8][4];
    #pragma unroll
    for (int mf=0;mf<2;mf++)
        #pragma unroll
        for (int nf=0;nf<8;nf++)
            #pragma unroll
            for (int e=0;e<4;e++) acc[mf][nf][e]=0.f;

    int nst = K >> 5;
    #pragma unroll
    for (int p = 0; p < 2; p++) {
        uint32_t st = sbase + (uint32_t)p*STG_BYTES;
        size_t k0 = (size_t)p*32;
        cp16(st + wA0, Ag0 + k0);
        cp16(st + wA1, Ag1 + k0);
        cp16(st + ASTG + wA0, Bg0 + k0);
        cp16(st + ASTG + wA1, Bg1 + k0);
        CP_COMMIT();
    }

    for (int s = 0; s < nst; s++) {
        uint32_t sb0 = sbase + (uint32_t)(s % 3)*STG_BYTES;
        CP_WAIT1();
        __syncthreads();
        #pragma unroll
        for (int j = 0; j < 2; j++) {
            uint32_t jx = (uint32_t)(j << 5);
            uint32_t a0[4], a1[4], bq[4][4];
            ldm4(a0, sb0 + (aoff[0] ^ jx));
            ldm4(a1, sb0 + (aoff[1] ^ jx));
            #pragma unroll
            for (int nt = 0; nt < 4; nt++) ldm4(bq[nt], sb0 + (boff[nt] ^ jx));
            #pragma unroll
            for (int nt = 0; nt < 4; nt++) {
                mma16(acc[0][2*nt],   a0, bq[nt][0], bq[nt][2]);
                mma16(acc[0][2*nt+1], a0, bq[nt][1], bq[nt][3]);
                mma16(acc[1][2*nt],   a1, bq[nt][0], bq[nt][2]);
                mma16(acc[1][2*nt+1], a1, bq[nt][1], bq[nt][3]);
            }
        }
        if (s + 2 < nst) {
            uint32_t st = sbase + (uint32_t)((s + 2) % 3)*STG_BYTES;
            size_t k0 = (size_t)(s + 2)*32;
            cp16(st + wA0, Ag0 + k0);
            cp16(st + wA1, Ag1 + k0);
            cp16(st + ASTG + wA0, Bg0 + k0);
            cp16(st + ASTG + wA1, Bg1 + k0);
        }
        CP_COMMIT();
    }

    // epilogue: lane (g,t); acc[.][nf]: n = wn + nf*8 + 2t, rows g / g+8
    #pragma unroll
    for (int mf=0;mf<2;mf++) {
        int m = bm + wm + mf*16 + g;
        #pragma unroll
        for (int nf=0;nf<8;nf++) {
            int n0 = bn + wn + nf*8 + 2*t;
            float bb0 = (n0   < Nreal) ? bias[n0]   : 0.f;
            float bb1 = (n0+1 < Nreal) ? bias[n0+1] : 0.f;
            float v0 = acc[mf][nf][0] + bb0;
            float v1 = acc[mf][nf][1] + bb1;
            float v2 = acc[mf][nf][2] + bb0;
            float v3 = acc[mf][nf][3] + bb1;
            if (doRelu) {
                v0=fmaxf(v0,0.f); v1=fmaxf(v1,0.f);
                v2=fmaxf(v2,0.f); v3=fmaxf(v3,0.f);
            }
            if (outHalf) {
                __half2* C = (__half2*)Cv;
                C[((size_t)m*ldc + n0) >> 1]     = __floats2half2_rn(v0, v1);
                C[((size_t)(m+8)*ldc + n0) >> 1] = __floats2half2_rn(v2, v3);
            } else {
                float* C = (float*)Cv;
                *(float2*)(C + (size_t)m*ldc + n0)     = make_float2(v0, v1);
                *(float2*)(C + (size_t)(m+8)*ldc + n0) = make_float2(v2, v3);
            }
        }
    }
}

// ============================================================================
// LayerNorm + ReLU over rows of 1024: fp32 in, fp16 out.
// ============================================================================
__global__ void ln_relu_kernel(const float* __restrict__ X, const float* __restrict__ g,
                               const float* __restrict__ beta, __half* __restrict__ Y)
{
    int b = blockIdx.x, tid = threadIdx.x;
    const float* x = X + (size_t)b*TH;
    __half* y = Y + (size_t)b*TH;
    float v[4], s = 0.f, s2 = 0.f;
    #pragma unroll
    for (int i=0;i<4;i++){ v[i]=x[tid + i*256]; s+=v[i]; s2+=v[i]*v[i]; }
    __shared__ float red[2][8];
    for (int o=16;o;o>>=1){ s += __shfl_xor_sync(0xffffffffu,s,o); s2 += __shfl_xor_sync(0xffffffffu,s2,o); }
    if ((tid&31)==0){ red[0][tid>>5]=s; red[1][tid>>5]=s2; }
    __syncthreads();
    float ts=0.f, ts2=0.f;
    #pragma unroll
    for (int w=0;w<8;w++){ ts+=red[0][w]; ts2+=red[1][w]; }
    float mean = ts*(1.f/TH);
    float var  = ts2*(1.f/TH) - mean*mean;
    float inv  = rsqrtf(var + 1e-5f);
    #pragma unroll
    for (int i=0;i<4;i++){
        int c = tid + i*256;
        float r = (v[i]-mean)*inv*g[c] + beta[c];
        y[c] = __float2half(fmaxf(r, 0.f));
    }
}

// ============================================================================
// Dueling combine + softmax over atoms (val ld=128 fp32, adv ld=4224 fp32)
// ============================================================================
__global__ void combine_kernel(const float* __restrict__ val, const float* __restrict__ adv,
                               float* __restrict__ out)
{
    int b = blockIdx.x, tid = threadIdx.x;
    __shared__ float sadv[ADVN];
    __shared__ float sval[ATOMS];
    __shared__ float cmean[ATOMS];
    const float* arow = adv + (size_t)b*ADVP;
    for (int i = tid; i < ADVN; i += 256) sadv[i] = arow[i];
    if (tid < ATOMS) sval[tid] = val[(size_t)b*128 + tid];
    __syncthreads();
    if (tid < ATOMS) {
        float s = 0.f;
        for (int a = 0; a < ACTIONS; a++) s += sadv[a*ATOMS + tid];
        cmean[tid] = s * (1.f/ACTIONS);
    }
    __syncthreads();
    float* orow = out + (size_t)b*ADVN;
    for (int a = tid; a < ACTIONS; a += 256) {
        float q[ATOMS];
        float mx = -1e30f;
        #pragma unroll
        for (int t = 0; t < ATOMS; t++) {
            float qv = sval[t] + sadv[a*ATOMS+t] - cmean[t];
            q[t] = qv; mx = fmaxf(mx, qv);
        }
        float sum = 0.f;
        #pragma unroll
        for (int t = 0; t < ATOMS; t++) { float e = fexp(q[t]-mx); q[t]=e; sum += e; }
        float inv = 1.f/sum;
        #pragma unroll
        for (int t = 0; t < ATOMS; t++) orow[a*ATOMS+t] = q[t]*inv;
    }
}

// ============================================================================
extern "C" void kernel_launch(void* const* d_in, const int* in_sizes, int n_in,
                              void* d_out, int out_size)
{
    const float* state = (const float*)d_in[0];
    const float* embW  = (const float*)d_in[1];
    const float* embB  = (const float*)d_in[2];
    const float* lng   = (const float*)d_in[3];
    const float* lnb   = (const float*)d_in[4];
    const float* cls   = (const float*)d_in[5];
    const float* ipW   = (const float*)d_in[6];
    const float* ipb   = (const float*)d_in[7];
    const float* opW   = (const float*)d_in[8];
    const float* opb   = (const float*)d_in[9];
    const float* t0W   = (const float*)d_in[10];
    const float* t0b   = (const float*)d_in[11];
    const float* t0g   = (const float*)d_in[12];
    const float* t0be  = (const float*)d_in[13];
    const float* t1W   = (const float*)d_in[14];
    const float* t1b   = (const float*)d_in[15];
    const float* t1g   = (const float*)d_in[16];
    const float* t1be  = (const float*)d_in[17];
    const float* vfW   = (const float*)d_in[18];
    const float* vfb   = (const float*)d_in[19];
    const float* voW   = (const float*)d_in[20];
    const float* vob   = (const float*)d_in[21];
    const float* afW   = (const float*)d_in[22];
    const float* afb   = (const float*)d_in[23];
    const float* aoW   = (const float*)d_in[24];
    const float* aob   = (const float*)d_in[25];
    float* out = (float*)d_out;

    __half *tin, *h, *vfc, *afc;
    float *pre, *valb, *advb;
    __half *t0Wt, *t1Wt, *vfWt, *afWt, *voWt, *aoWt;
    cudaGetSymbolAddress((void**)&tin,  g_tin);
    cudaGetSymbolAddress((void**)&pre,  g_pre);
    cudaGetSymbolAddress((void**)&h,    g_h);
    cudaGetSymbolAddress((void**)&vfc,  g_vfc);
    cudaGetSymbolAddress((void**)&afc,  g_afc);
    cudaGetSymbolAddress((void**)&valb, g_val);
    cudaGetSymbolAddress((void**)&advb, g_adv);
    cudaGetSymbolAddress((void**)&t0Wt, g_t0Wt);
    cudaGetSymbolAddress((void**)&t1Wt, g_t1Wt);
    cudaGetSymbolAddress((void**)&vfWt, g_vfWt);
    cudaGetSymbolAddress((void**)&afWt, g_afWt);
    cudaGetSymbolAddress((void**)&voWt, g_voWt);
    cudaGetSymbolAddress((void**)&aoWt, g_aoWt);

    setup_kernel<<<1, 1024>>>(embW, embB, lng, lnb, cls, ipW, ipb, opW);
    front_kernel<<<BATCH, 128>>>(state, opb);

    dim3 tb(32, 8);
    transpose_pad_kernel<<<dim3(TIN_PAD/32, 1024/32), tb>>>(t0W, 1488, 1024, t0Wt, TIN_PAD);
    transpose_pad_kernel<<<dim3(1024/32,    1024/32), tb>>>(t1W, 1024, 1024, t1Wt, 1024);
    transpose_pad_kernel<<<dim3(1024/32,     512/32), tb>>>(vfW, 1024,  512, vfWt, 1024);
    transpose_pad_kernel<<<dim3(1024/32,     512/32), tb>>>(afW, 1024,  512, afWt, 1024);
    transpose_pad_kernel<<<dim3( 512/32,     128/32), tb>>>(voW,  512, ATOMS, voWt, 512);
    transpose_pad_kernel<<<dim3( 512/32,    ADVP/32), tb>>>(aoW,  512, ADVN, aoWt, 512);

    // t0: [8192,1536] @ [1536,1024] -> fp32 pre
    hgemm_kernel<<<dim3(1024/128, BATCH/128), 256>>>(
        TIN_PAD, tin, TIN_PAD, t0Wt, pre, TH, TH, t0b, 0, 0);
    ln_relu_kernel<<<BATCH, 256>>>(pre, t0g, t0be, h);

    // t1
    hgemm_kernel<<<dim3(1024/128, BATCH/128), 256>>>(
        TH, h, TH, t1Wt, pre, TH, TH, t1b, 0, 0);
    ln_relu_kernel<<<BATCH, 256>>>(pre, t1g, t1be, h);

    // value / advantage fc (relu, fp16 out)
    hgemm_kernel<<<dim3(512/128, BATCH/128), 256>>>(
        TH, h, TH, vfWt, vfc, 512, 512, vfb, 1, 1);
    hgemm_kernel<<<dim3(512/128, BATCH/128), 256>>>(
        TH, h, TH, afWt, afc, 512, 512, afb, 1, 1);

    // heads (fp32 out)
    hgemm_kernel<<<dim3(128/128, BATCH/128), 256>>>(
        512, vfc, 512, voWt, valb, 128, ATOMS, vob, 0, 0);
    hgemm_kernel<<<dim3(ADVP/128, BATCH/128), 256>>>(
        512, afc, 512, aoWt, advb, ADVP, ADVN, aob, 0, 0);

    combine_kernel<<<BATCH, 256>>>(valb, advb, out);
}